// round 1
// baseline (speedup 1.0000x reference)
#include <cuda_runtime.h>
#include <math.h>

// ---------------- problem constants ----------------
constexpr int BB      = 8;
constexpr int C_INC   = 64;
constexpr int HH      = 128;
constexpr int WW      = 128;
constexpr int NPOINT  = 128;
constexpr int NINST   = 512;
constexpr int DMODEL  = 256;
constexpr int P1      = 129;   // stage-1 tokens (center + 128 points)
constexpr int P2      = 128;
constexpr int FEATC   = 254;
constexpr int FEATPAD = 256;   // padded channel stride for NHWC feature maps
constexpr int PIX     = BB * HH * WW;     // 131072
constexpr int T1      = NINST * P1;       // 66048
constexpr int T2      = NINST * P2;       // 65536

// ---------------- scratch (device globals; no allocations) ----------------
__device__ float g_tmp  [ (size_t)PIX * 256 ];       // conv3x3 output, NHWC
__device__ float g_feat1[ (size_t)PIX * FEATPAD ];   // NHWC, 254 valid ch
__device__ float g_feat2[ (size_t)PIX * FEATPAD ];
__device__ float g_pts1 [ NINST * P1 * 2 ];
__device__ float g_init [ NINST * NPOINT * 2 ];
__device__ float g_coarse[ NINST * NPOINT * 2 ];
__device__ float g_nrm  [ NINST * 4 ];               // mx, my, 1/scale
__device__ float g_x    [ (size_t)T1 * DMODEL ];
__device__ float g_qkv  [ (size_t)T1 * 3 * DMODEL ];
__device__ float g_att  [ (size_t)T1 * DMODEL ];
__device__ float g_wp1  [ 514 ];                     // fused wo*whead (256x2) + bias (2)
__device__ float g_wp2  [ 514 ];

// ---------------- fused head weights: W' = wo @ whead, b' = bo @ whead + bhead ----------------
__global__ void fuse_head_kernel(const float* __restrict__ wo, const float* __restrict__ bo,
                                 const float* __restrict__ wh, const float* __restrict__ bh,
                                 float* __restrict__ wp)
{
    int c = threadIdx.x;  // 256 threads
    float s0 = 0.f, s1 = 0.f;
    for (int k = 0; k < 256; k++) {
        float w = wo[c * 256 + k];
        s0 += w * wh[2 * k];
        s1 += w * wh[2 * k + 1];
    }
    wp[2 * c] = s0;
    wp[2 * c + 1] = s1;
    if (c == 0) {
        float b0 = bh[0], b1 = bh[1];
        for (int k = 0; k < 256; k++) {
            b0 += bo[k] * wh[2 * k];
            b1 += bo[k] * wh[2 * k + 1];
        }
        wp[512] = b0;
        wp[513] = b1;
    }
}

// ---------------- init polys + points + first output region ----------------
__global__ void init_kernel(const float* __restrict__ wh, const int* __restrict__ ct_ind,
                            const int* __restrict__ ct_img, float* __restrict__ pts1,
                            float* __restrict__ initp, float* __restrict__ out0)
{
    int n = blockIdx.x;
    int p = threadIdx.x;   // 128
    int ci = ct_ind[n];
    int cx = ci % WW;
    int cy = ci / WW;
    int img = ct_img[n];
    size_t base = (((size_t)img * 256 + 2 * p) * HH + cy) * WW + cx;
    float ox = wh[base];
    float oy = wh[base + (size_t)HH * WW];   // channel 2p+1
    float fx = ox * 10.0f + (float)cx;
    float fy = oy * 10.0f + (float)cy;
    pts1[(n * P1 + 1 + p) * 2]     = fx;
    pts1[(n * P1 + 1 + p) * 2 + 1] = fy;
    if (p == 0) {
        pts1[n * P1 * 2]     = (float)cx;
        pts1[n * P1 * 2 + 1] = (float)cy;
    }
    int pidx = n * NPOINT + p;
    initp[pidx * 2]     = fx;
    initp[pidx * 2 + 1] = fy;
    out0[pidx * 2]     = fx * 4.0f;
    out0[pidx * 2 + 1] = fy * 4.0f;
}

// ---------------- conv3x3 (NCHW in -> NHWC out, pad=1, bias+relu) ----------------
// block: 256 threads = 8y x 32x pixels, 32 output channels; grid (64 tiles, 8 ocb, 8 b)
__global__ void conv3x3_kernel(const float* __restrict__ in, const float* __restrict__ w,
                               const float* __restrict__ bias, float* __restrict__ out)
{
    __shared__ float s_in[8 * 10 * 36];   // [cin][yy][xx], row stride 36
    __shared__ float s_w[72 * 33];        // [q = cin*9+tap][oc], stride 33 (conflict-free)

    int tid = threadIdx.x;
    int ty = tid >> 5;          // 0..7
    int tx = tid & 31;          // 0..31
    int ytile = blockIdx.x >> 2;
    int xtile = blockIdx.x & 3;
    int y0 = ytile * 8;
    int x0 = xtile * 32;
    int ocb = blockIdx.y;       // 0..7 (32 oc each)
    int b   = blockIdx.z;

    float acc[32];
#pragma unroll
    for (int oc = 0; oc < 32; oc++) acc[oc] = 0.f;

    for (int cb = 0; cb < C_INC; cb += 8) {
        // load input patch 8cin x 10 x 34 (zero-padded borders)
        for (int i = tid; i < 8 * 10 * 34; i += 256) {
            int c  = i / 340;
            int r  = i % 340;
            int yy = r / 34;
            int xx = r % 34;
            int gy = y0 + yy - 1;
            int gx = x0 + xx - 1;
            float v = 0.f;
            if (gy >= 0 && gy < HH && gx >= 0 && gx < WW)
                v = in[(((size_t)b * C_INC + cb + c) * HH + gy) * WW + gx];
            s_in[c * 360 + yy * 36 + xx] = v;
        }
        // load weights: 32 oc x 72 (8cin x 9tap) — contiguous 72-float runs per oc
        for (int i = tid; i < 32 * 72; i += 256) {
            int oc = i / 72;
            int q  = i % 72;
            s_w[q * 33 + oc] = w[(size_t)(ocb * 32 + oc) * 576 + cb * 9 + q];
        }
        __syncthreads();

        for (int cin = 0; cin < 8; cin++) {
#pragma unroll
            for (int ky = 0; ky < 3; ky++) {
#pragma unroll
                for (int kx = 0; kx < 3; kx++) {
                    float v = s_in[cin * 360 + (ty + ky) * 36 + (tx + kx)];
                    const float* wrow = &s_w[(cin * 9 + ky * 3 + kx) * 33];
#pragma unroll
                    for (int oc = 0; oc < 32; oc++)
                        acc[oc] += v * wrow[oc];
                }
            }
        }
        __syncthreads();
    }

    int y = y0 + ty, x = x0 + tx;
    size_t obase = (((size_t)b * HH + y) * WW + x) * 256 + ocb * 32;
#pragma unroll
    for (int oc = 0; oc < 32; oc++) {
        float r = acc[oc] + bias[ocb * 32 + oc];
        out[obase + oc] = fmaxf(r, 0.f);
    }
}

// ---------------- SGEMM with bias: C[M x N] = A[M x K] * B (+bias) ----------------
// TB=false: B is [K][N] row-major (requires N % 64 == 0). TB=true: B is [N][K].
// BM=128, BN=64, BK=16, 256 threads, 8x4 microtile. M%128==0, K%16==0 assumed.
template <bool TB>
__global__ void sgemm_kernel(const float* __restrict__ A, const float* __restrict__ Bm,
                             const float* __restrict__ bias, float* __restrict__ C,
                             int M, int N, int K, int ldc)
{
    __shared__ float As[16][132];
    __shared__ float Bs[16][68];

    int tid = threadIdx.x;
    int tx = tid & 15;
    int ty = tid >> 4;
    int bx = blockIdx.x;
    int by = blockIdx.y;

    float acc[8][4];
#pragma unroll
    for (int i = 0; i < 8; i++)
#pragma unroll
        for (int j = 0; j < 4; j++) acc[i][j] = 0.f;

    int ar = tid >> 2;          // 0..63
    int ac = (tid & 3) * 4;     // 0,4,8,12

    for (int kt = 0; kt < K; kt += 16) {
#pragma unroll
        for (int half = 0; half < 2; half++) {
            int m = ar + half * 64;
            float4 av = *(const float4*)(A + (size_t)(by * 128 + m) * K + kt + ac);
            As[ac + 0][m] = av.x;
            As[ac + 1][m] = av.y;
            As[ac + 2][m] = av.z;
            As[ac + 3][m] = av.w;
        }
        if (TB) {
            int nn = tid >> 2;
            int kk = (tid & 3) * 4;
            int ng = bx * 64 + nn;
            float4 bv = make_float4(0.f, 0.f, 0.f, 0.f);
            if (ng < N) bv = *(const float4*)(Bm + (size_t)ng * K + kt + kk);
            Bs[kk + 0][nn] = bv.x;
            Bs[kk + 1][nn] = bv.y;
            Bs[kk + 2][nn] = bv.z;
            Bs[kk + 3][nn] = bv.w;
        } else {
            int kk = tid >> 4;
            int nn = (tid & 15) * 4;
            float4 bv = *(const float4*)(Bm + (size_t)(kt + kk) * N + bx * 64 + nn);
            *(float4*)&Bs[kk][nn] = bv;
        }
        __syncthreads();

#pragma unroll
        for (int k = 0; k < 16; k++) {
            float4 a0 = *(const float4*)&As[k][ty * 8];
            float4 a1 = *(const float4*)&As[k][ty * 8 + 4];
            float4 bq = *(const float4*)&Bs[k][tx * 4];
            float av[8] = {a0.x, a0.y, a0.z, a0.w, a1.x, a1.y, a1.z, a1.w};
            float bv[4] = {bq.x, bq.y, bq.z, bq.w};
#pragma unroll
            for (int i = 0; i < 8; i++)
#pragma unroll
                for (int j = 0; j < 4; j++)
                    acc[i][j] += av[i] * bv[j];
        }
        __syncthreads();
    }

#pragma unroll
    for (int i = 0; i < 8; i++) {
        float* crow = C + (size_t)(by * 128 + ty * 8 + i) * ldc + bx * 64 + tx * 4;
#pragma unroll
        for (int j = 0; j < 4; j++) {
            int col = bx * 64 + tx * 4 + j;
            if (col < N) crow[j] = acc[i][j] + bias[col];
        }
    }
}

// ---------------- per-instance normalization params (mean, max-abs scale) ----------------
__global__ void norm_kernel(const float* __restrict__ pts, int P, float* __restrict__ nrm)
{
    __shared__ float sx[128], sy[128];
    int n = blockIdx.x, tid = threadIdx.x;
    const float* base = pts + (size_t)n * P * 2;
    float ax = 0.f, ay = 0.f;
    for (int p = tid; p < P; p += 128) { ax += base[2 * p]; ay += base[2 * p + 1]; }
    sx[tid] = ax; sy[tid] = ay;
    __syncthreads();
    for (int s = 64; s > 0; s >>= 1) {
        if (tid < s) { sx[tid] += sx[tid + s]; sy[tid] += sy[tid + s]; }
        __syncthreads();
    }
    float mx = sx[0] / (float)P;
    float my = sy[0] / (float)P;
    __syncthreads();
    float am = 0.f;
    for (int p = tid; p < P; p += 128) {
        am = fmaxf(am, fmaxf(fabsf(base[2 * p] - mx), fabsf(base[2 * p + 1] - my)));
    }
    sx[tid] = am;
    __syncthreads();
    for (int s = 64; s > 0; s >>= 1) {
        if (tid < s) sx[tid] = fmaxf(sx[tid], sx[tid + s]);
        __syncthreads();
    }
    if (tid == 0) {
        nrm[n * 4]     = mx;
        nrm[n * 4 + 1] = my;
        nrm[n * 4 + 2] = 1.f / (sx[0] + 1e-6f);
    }
}

// ---------------- bilinear sample + build token features ----------------
// one warp per token; 254 feature channels + 2 normalized coords
__global__ void sample_kernel(const float* __restrict__ feat, const float* __restrict__ pts,
                              const int* __restrict__ img_idx, const float* __restrict__ nrm,
                              float* __restrict__ xout, int P, int T)
{
    int warp = threadIdx.x >> 5;
    int lane = threadIdx.x & 31;
    int t = blockIdx.x * 8 + warp;
    if (t >= T) return;
    int n = t / P;
    float px = pts[t * 2], py = pts[t * 2 + 1];
    int img = img_idx[n];
    float ix = px - 0.5f, iy = py - 0.5f;
    float x0f = floorf(ix), y0f = floorf(iy);
    float wx = ix - x0f, wy = iy - y0f;
    int x0 = (int)x0f, y0 = (int)y0f;
    float w00 = (1.f - wx) * (1.f - wy);
    float w10 = wx * (1.f - wy);
    float w01 = (1.f - wx) * wy;
    float w11 = wx * wy;
    bool vx0 = (x0 >= 0 && x0 < WW), vx1 = (x0 + 1 >= 0 && x0 + 1 < WW);
    bool vy0 = (y0 >= 0 && y0 < HH), vy1 = (y0 + 1 >= 0 && y0 + 1 < HH);
    if (!(vx0 && vy0)) w00 = 0.f;
    if (!(vx1 && vy0)) w10 = 0.f;
    if (!(vx0 && vy1)) w01 = 0.f;
    if (!(vx1 && vy1)) w11 = 0.f;
    int xc0 = min(max(x0, 0), WW - 1), xc1 = min(max(x0 + 1, 0), WW - 1);
    int yc0 = min(max(y0, 0), HH - 1), yc1 = min(max(y0 + 1, 0), HH - 1);
    size_t b00 = (((size_t)img * HH + yc0) * WW + xc0) * FEATPAD;
    size_t b10 = (((size_t)img * HH + yc0) * WW + xc1) * FEATPAD;
    size_t b01 = (((size_t)img * HH + yc1) * WW + xc0) * FEATPAD;
    size_t b11 = (((size_t)img * HH + yc1) * WW + xc1) * FEATPAD;
    float* xr = xout + (size_t)t * DMODEL;
    for (int c = lane; c < FEATC; c += 32) {
        xr[c] = w00 * feat[b00 + c] + w10 * feat[b10 + c] +
                w01 * feat[b01 + c] + w11 * feat[b11 + c];
    }
    if (lane == 0) {
        float mx = nrm[n * 4], my = nrm[n * 4 + 1], inv = nrm[n * 4 + 2];
        xr[254] = (px - mx) * inv;
        xr[255] = (py - my) * inv;
    }
}

// ---------------- attention: flash-style online softmax, block per (inst, head) ----------------
__global__ void attn_kernel(const float* __restrict__ qkv, float* __restrict__ att, int P)
{
    __shared__ float4 k_s[P1 * 8];
    __shared__ float4 v_s[P1 * 8];
    int n = blockIdx.x, h = blockIdx.y;
    int tid = threadIdx.x;   // 128

    for (int i = tid; i < P * 8; i += 128) {
        int p = i >> 3, c = i & 7;
        const float* row = qkv + (size_t)(n * P + p) * 768 + h * 32;
        k_s[i] = ((const float4*)(row + 256))[c];
        v_s[i] = ((const float4*)(row + 512))[c];
    }
    __syncthreads();

    const float QS = 0.17677669529663689f * 1.44269504088896340f;  // (1/sqrt(32)) * log2(e)
    for (int p = tid; p < P; p += 128) {
        const float4* qrow = (const float4*)(qkv + (size_t)(n * P + p) * 768 + h * 32);
        float q[32];
#pragma unroll
        for (int c = 0; c < 8; c++) {
            float4 tq = qrow[c];
            q[4 * c]     = tq.x * QS;
            q[4 * c + 1] = tq.y * QS;
            q[4 * c + 2] = tq.z * QS;
            q[4 * c + 3] = tq.w * QS;
        }
        float m = -INFINITY, l = 0.f;
        float o[32];
#pragma unroll
        for (int d = 0; d < 32; d++) o[d] = 0.f;

        for (int j = 0; j < P; j++) {
            const float* kr = (const float*)&k_s[j * 8];
            float s0 = 0.f, s1 = 0.f, s2 = 0.f, s3 = 0.f;
#pragma unroll
            for (int d = 0; d < 32; d += 4) {
                s0 += q[d] * kr[d];
                s1 += q[d + 1] * kr[d + 1];
                s2 += q[d + 2] * kr[d + 2];
                s3 += q[d + 3] * kr[d + 3];
            }
            float s = (s0 + s1) + (s2 + s3);
            if (s > m) {
                float corr = exp2f(m - s);
                m = s;
                l *= corr;
#pragma unroll
                for (int d = 0; d < 32; d++) o[d] *= corr;
            }
            float pw = exp2f(s - m);
            l += pw;
            const float* vr = (const float*)&v_s[j * 8];
#pragma unroll
            for (int d = 0; d < 32; d++) o[d] += pw * vr[d];
        }
        float inv = 1.f / l;
        float* orow = att + (size_t)(n * P + p) * 256 + h * 32;
#pragma unroll
        for (int d = 0; d < 32; d++) orow[d] = o[d] * inv;
    }
}

// ---------------- fused head projection + polygon update + scaled output ----------------
__global__ void head_kernel(const float* __restrict__ att, const float* __restrict__ wp,
                            const float* __restrict__ polyin, float* __restrict__ polyout,
                            float* __restrict__ outp, float strideF, int P, int stage1, int T)
{
    __shared__ float s_wp[514];
    for (int i = threadIdx.x; i < 514; i += 128) s_wp[i] = wp[i];
    __syncthreads();
    int warp = threadIdx.x >> 5;
    int lane = threadIdx.x & 31;
    int t = blockIdx.x * 4 + warp;
    if (t >= T) return;
    int n = t / P, p = t % P;
    const float* ar = att + (size_t)t * 256;
    float a0 = 0.f, a1 = 0.f;
    for (int c = lane; c < 256; c += 32) {
        float av = ar[c];
        a0 += av * s_wp[2 * c];
        a1 += av * s_wp[2 * c + 1];
    }
#pragma unroll
    for (int off = 16; off; off >>= 1) {
        a0 += __shfl_down_sync(0xffffffffu, a0, off);
        a1 += __shfl_down_sync(0xffffffffu, a1, off);
    }
    if (lane == 0) {
        if (stage1 && p == 0) return;
        int pidx = stage1 ? (n * NPOINT + p - 1) : (n * NPOINT + p);
        float ox = a0 + s_wp[512];
        float oy = a1 + s_wp[513];
        float rx = ox * strideF + polyin[pidx * 2];
        float ry = oy * strideF + polyin[pidx * 2 + 1];
        if (polyout) {
            polyout[pidx * 2]     = rx;
            polyout[pidx * 2 + 1] = ry;
        }
        outp[pidx * 2]     = rx * 4.0f;
        outp[pidx * 2 + 1] = ry * 4.0f;
    }
}

// ---------------- launch ----------------
extern "C" void kernel_launch(void* const* d_in, const int* in_sizes, int n_in,
                              void* d_out, int out_size)
{
    const float* cnn     = (const float*)d_in[0];
    const float* wh      = (const float*)d_in[1];
    const int*   ct_ind  = (const int*)  d_in[2];
    const int*   ct_img  = (const int*)  d_in[3];
    const float* f1_w1   = (const float*)d_in[4];
    const float* f1_b1   = (const float*)d_in[5];
    const float* f1_w2   = (const float*)d_in[6];
    const float* f1_b2   = (const float*)d_in[7];
    const float* f2_w1   = (const float*)d_in[8];
    const float* f2_b1   = (const float*)d_in[9];
    const float* f2_w2   = (const float*)d_in[10];
    const float* f2_b2   = (const float*)d_in[11];
    const float* c1_wqkv = (const float*)d_in[12];
    const float* c1_bqkv = (const float*)d_in[13];
    const float* c1_wo   = (const float*)d_in[14];
    const float* c1_bo   = (const float*)d_in[15];
    const float* c1_wh   = (const float*)d_in[16];
    const float* c1_bh   = (const float*)d_in[17];
    const float* c2_wqkv = (const float*)d_in[18];
    const float* c2_bqkv = (const float*)d_in[19];
    const float* c2_wo   = (const float*)d_in[20];
    const float* c2_bo   = (const float*)d_in[21];
    const float* c2_wh   = (const float*)d_in[22];
    const float* c2_bh   = (const float*)d_in[23];
    float* out = (float*)d_out;

    void *p_tmp, *p_feat1, *p_feat2, *p_pts1, *p_init, *p_coarse, *p_nrm;
    void *p_x, *p_qkv, *p_att, *p_wp1, *p_wp2;
    cudaGetSymbolAddress(&p_tmp, g_tmp);
    cudaGetSymbolAddress(&p_feat1, g_feat1);
    cudaGetSymbolAddress(&p_feat2, g_feat2);
    cudaGetSymbolAddress(&p_pts1, g_pts1);
    cudaGetSymbolAddress(&p_init, g_init);
    cudaGetSymbolAddress(&p_coarse, g_coarse);
    cudaGetSymbolAddress(&p_nrm, g_nrm);
    cudaGetSymbolAddress(&p_x, g_x);
    cudaGetSymbolAddress(&p_qkv, g_qkv);
    cudaGetSymbolAddress(&p_att, g_att);
    cudaGetSymbolAddress(&p_wp1, g_wp1);
    cudaGetSymbolAddress(&p_wp2, g_wp2);
    float* tmp    = (float*)p_tmp;
    float* feat1  = (float*)p_feat1;
    float* feat2  = (float*)p_feat2;
    float* pts1   = (float*)p_pts1;
    float* initp  = (float*)p_init;
    float* coarse = (float*)p_coarse;
    float* nrm    = (float*)p_nrm;
    float* xbuf   = (float*)p_x;
    float* qkv    = (float*)p_qkv;
    float* att    = (float*)p_att;
    float* wp1    = (float*)p_wp1;
    float* wp2    = (float*)p_wp2;

    // fused head weights (kills both 256x256 o-proj GEMMs)
    fuse_head_kernel<<<1, 256>>>(c1_wo, c1_bo, c1_wh, c1_bh, wp1);
    fuse_head_kernel<<<1, 256>>>(c2_wo, c2_bo, c2_wh, c2_bh, wp2);

    // init polys, stage-1 points, output region 0
    init_kernel<<<NINST, 128>>>(wh, ct_ind, ct_img, pts1, initp, out);

    // feature pyramids: conv3x3+relu -> NHWC tmp, then 1x1 as GEMM (B transposed)
    conv3x3_kernel<<<dim3(64, 8, 8), 256>>>(cnn, f1_w1, f1_b1, tmp);
    sgemm_kernel<true><<<dim3(4, PIX / 128), 256>>>(tmp, f1_w2, f1_b2, feat1,
                                                    PIX, FEATC, 256, FEATPAD);
    conv3x3_kernel<<<dim3(64, 8, 8), 256>>>(cnn, f2_w1, f2_b1, tmp);
    sgemm_kernel<true><<<dim3(4, PIX / 128), 256>>>(tmp, f2_w2, f2_b2, feat2,
                                                    PIX, FEATC, 256, FEATPAD);

    // ---- stage 1 ----
    norm_kernel<<<NINST, 128>>>(pts1, P1, nrm);
    sample_kernel<<<(T1 + 7) / 8, 256>>>(feat1, pts1, ct_img, nrm, xbuf, P1, T1);
    sgemm_kernel<false><<<dim3(12, T1 / 128), 256>>>(xbuf, c1_wqkv, c1_bqkv, qkv,
                                                     T1, 768, 256, 768);
    attn_kernel<<<dim3(NINST, 8), 128>>>(qkv, att, P1);
    head_kernel<<<(T1 + 3) / 4, 128>>>(att, wp1, initp, coarse,
                                       out + NINST * NPOINT * 2, 4.0f, P1, 1, T1);

    // ---- stage 2 ----
    norm_kernel<<<NINST, 128>>>(coarse, P2, nrm);
    sample_kernel<<<(T2 + 7) / 8, 256>>>(feat2, coarse, ct_img, nrm, xbuf, P2, T2);
    sgemm_kernel<false><<<dim3(12, T2 / 128), 256>>>(xbuf, c2_wqkv, c2_bqkv, qkv,
                                                     T2, 768, 256, 768);
    attn_kernel<<<dim3(NINST, 8), 128>>>(qkv, att, P2);
    head_kernel<<<(T2 + 3) / 4, 128>>>(att, wp2, coarse, nullptr,
                                       out + 2 * NINST * NPOINT * 2, 1.0f, P2, 0, T2);
}

// round 2
// speedup vs baseline: 1.3377x; 1.3377x over previous
#include <cuda_runtime.h>
#include <math.h>

// ---------------- problem constants ----------------
constexpr int BB      = 8;
constexpr int C_INC   = 64;
constexpr int HH      = 128;
constexpr int WW      = 128;
constexpr int NPOINT  = 128;
constexpr int NINST   = 512;
constexpr int DMODEL  = 256;
constexpr int P1      = 129;
constexpr int P2      = 128;
constexpr int FEATC   = 254;
constexpr int FEATPAD = 256;
constexpr int PIX     = BB * HH * WW;     // 131072
constexpr int T1      = NINST * P1;       // 66048
constexpr int T2      = NINST * P2;       // 65536

// ---------------- scratch ----------------
__device__ float g_tmp  [ (size_t)PIX * 256 ];
__device__ float g_feat1[ (size_t)PIX * FEATPAD ];
__device__ float g_feat2[ (size_t)PIX * FEATPAD ];
__device__ float g_pts1 [ NINST * P1 * 2 ];
__device__ float g_init [ NINST * NPOINT * 2 ];
__device__ float g_coarse[ NINST * NPOINT * 2 ];
__device__ float g_nrm  [ NINST * 4 ];
__device__ float g_x    [ (size_t)T1 * DMODEL ];
__device__ float g_qkv  [ (size_t)T1 * 3 * DMODEL ];
__device__ float g_att  [ (size_t)T1 * DMODEL ];
__device__ float g_wp1  [ 514 ];
__device__ float g_wp2  [ 514 ];

// ---------------- fused head weights ----------------
__global__ void fuse_head_kernel(const float* __restrict__ wo, const float* __restrict__ bo,
                                 const float* __restrict__ wh, const float* __restrict__ bh,
                                 float* __restrict__ wp)
{
    int c = threadIdx.x;
    float s0 = 0.f, s1 = 0.f;
    for (int k = 0; k < 256; k++) {
        float w = wo[c * 256 + k];
        s0 += w * wh[2 * k];
        s1 += w * wh[2 * k + 1];
    }
    wp[2 * c] = s0;
    wp[2 * c + 1] = s1;
    if (c == 0) {
        float b0 = bh[0], b1 = bh[1];
        for (int k = 0; k < 256; k++) {
            b0 += bo[k] * wh[2 * k];
            b1 += bo[k] * wh[2 * k + 1];
        }
        wp[512] = b0;
        wp[513] = b1;
    }
}

// ---------------- init ----------------
__global__ void init_kernel(const float* __restrict__ wh, const int* __restrict__ ct_ind,
                            const int* __restrict__ ct_img, float* __restrict__ pts1,
                            float* __restrict__ initp, float* __restrict__ out0)
{
    int n = blockIdx.x;
    int p = threadIdx.x;
    int ci = ct_ind[n];
    int cx = ci % WW;
    int cy = ci / WW;
    int img = ct_img[n];
    size_t base = (((size_t)img * 256 + 2 * p) * HH + cy) * WW + cx;
    float ox = wh[base];
    float oy = wh[base + (size_t)HH * WW];
    float fx = ox * 10.0f + (float)cx;
    float fy = oy * 10.0f + (float)cy;
    pts1[(n * P1 + 1 + p) * 2]     = fx;
    pts1[(n * P1 + 1 + p) * 2 + 1] = fy;
    if (p == 0) {
        pts1[n * P1 * 2]     = (float)cx;
        pts1[n * P1 * 2 + 1] = (float)cy;
    }
    int pidx = n * NPOINT + p;
    initp[pidx * 2]     = fx;
    initp[pidx * 2 + 1] = fy;
    out0[pidx * 2]     = fx * 4.0f;
    out0[pidx * 2 + 1] = fy * 4.0f;
}

// ---------------- conv3x3: NCHW->NHWC, pad 1, bias+relu ----------------
// 256 threads; tile 16y x 32x; each thread: 2 pixels (y, y+8) x 32 oc.
// s_w row stride 36 floats = 144B (16B aligned) -> LDS.128 broadcast reads.
__global__ __launch_bounds__(256, 2)
void conv3x3_kernel(const float* __restrict__ in, const float* __restrict__ w,
                    const float* __restrict__ bias, float* __restrict__ out)
{
    __shared__ __align__(16) float s_in[8 * 18 * 36];   // [cin][yy(18)][xx stride 36]
    __shared__ __align__(16) float s_w[72 * 36];        // [q = cin*9+tap][oc], stride 36

    int tid = threadIdx.x;
    int ty = tid >> 5;          // 0..7
    int tx = tid & 31;          // 0..31
    int ytile = blockIdx.x >> 2;   // 0..7
    int xtile = blockIdx.x & 3;    // 0..3
    int y0 = ytile * 16;
    int x0 = xtile * 32;
    int ocb = blockIdx.y;       // 0..7
    int b   = blockIdx.z;

    float acc0[32], acc1[32];
#pragma unroll
    for (int oc = 0; oc < 32; oc++) { acc0[oc] = 0.f; acc1[oc] = 0.f; }

    for (int cb = 0; cb < C_INC; cb += 8) {
        // input patch: 8 cin x 18 rows x 34 cols (zero-padded)
        for (int i = tid; i < 8 * 18 * 34; i += 256) {
            int c  = i / 612;
            int r  = i % 612;
            int yy = r / 34;
            int xx = r % 34;
            int gy = y0 + yy - 1;
            int gx = x0 + xx - 1;
            float v = 0.f;
            if (gy >= 0 && gy < HH && gx >= 0 && gx < WW)
                v = in[(((size_t)b * C_INC + cb + c) * HH + gy) * WW + gx];
            s_in[c * 648 + yy * 36 + xx] = v;
        }
        // weights: 32 oc x 72 q
        for (int i = tid; i < 32 * 72; i += 256) {
            int oc = i / 72;
            int q  = i % 72;
            s_w[q * 36 + oc] = w[(size_t)(ocb * 32 + oc) * 576 + cb * 9 + q];
        }
        __syncthreads();

        for (int cin = 0; cin < 8; cin++) {
#pragma unroll
            for (int ky = 0; ky < 3; ky++) {
#pragma unroll
                for (int kx = 0; kx < 3; kx++) {
                    float v0 = s_in[cin * 648 + (ty + ky) * 36 + (tx + kx)];
                    float v1 = s_in[cin * 648 + (ty + 8 + ky) * 36 + (tx + kx)];
                    const float4* w4 = (const float4*)&s_w[(cin * 9 + ky * 3 + kx) * 36];
#pragma unroll
                    for (int j = 0; j < 8; j++) {
                        float4 wv = w4[j];
                        acc0[4 * j]     += v0 * wv.x;
                        acc0[4 * j + 1] += v0 * wv.y;
                        acc0[4 * j + 2] += v0 * wv.z;
                        acc0[4 * j + 3] += v0 * wv.w;
                        acc1[4 * j]     += v1 * wv.x;
                        acc1[4 * j + 1] += v1 * wv.y;
                        acc1[4 * j + 2] += v1 * wv.z;
                        acc1[4 * j + 3] += v1 * wv.w;
                    }
                }
            }
        }
        __syncthreads();
    }

    int x = x0 + tx;
    size_t ob0 = (((size_t)b * HH + (y0 + ty)) * WW + x) * 256 + ocb * 32;
    size_t ob1 = (((size_t)b * HH + (y0 + ty + 8)) * WW + x) * 256 + ocb * 32;
#pragma unroll
    for (int oc = 0; oc < 32; oc++) {
        float bv = bias[ocb * 32 + oc];
        out[ob0 + oc] = fmaxf(acc0[oc] + bv, 0.f);
        out[ob1 + oc] = fmaxf(acc1[oc] + bv, 0.f);
    }
}

// ---------------- SGEMM: C[MxN] = A[MxK] * B (+bias) ----------------
// 128x128 tile, BK=16, 256 threads, 8x8 microtile. M%128==0, K%16==0.
// TB=false: B is [K][N] row-major, N%8==0. TB=true: B is [N][K] (1x1 conv weights).
template <bool TB>
__global__ __launch_bounds__(256, 2)
void sgemm_kernel(const float* __restrict__ A, const float* __restrict__ Bm,
                  const float* __restrict__ bias, float* __restrict__ C,
                  int M, int N, int K, int ldc)
{
    __shared__ __align__(16) float As[16][132];
    __shared__ __align__(16) float Bs[16][132];

    int tid = threadIdx.x;
    int tx = tid & 15;
    int ty = tid >> 4;
    int bx = blockIdx.x;
    int by = blockIdx.y;

    float acc[8][8];
#pragma unroll
    for (int i = 0; i < 8; i++)
#pragma unroll
        for (int j = 0; j < 8; j++) acc[i][j] = 0.f;

    int ar = tid >> 1;            // 0..127
    int ac = (tid & 1) * 8;       // 0 or 8

    for (int kt = 0; kt < K; kt += 16) {
        // A tile: 128 rows x 16 k  (transpose into As[k][m])
        {
            const float* ap = A + (size_t)(by * 128 + ar) * K + kt + ac;
            float4 a0 = *(const float4*)(ap);
            float4 a1 = *(const float4*)(ap + 4);
            As[ac + 0][ar] = a0.x; As[ac + 1][ar] = a0.y;
            As[ac + 2][ar] = a0.z; As[ac + 3][ar] = a0.w;
            As[ac + 4][ar] = a1.x; As[ac + 5][ar] = a1.y;
            As[ac + 6][ar] = a1.z; As[ac + 7][ar] = a1.w;
        }
        if (TB) {
            int nn = tid >> 1;          // 0..127
            int kc = (tid & 1) * 8;
            int ng = bx * 128 + nn;
            float4 b0 = make_float4(0.f,0.f,0.f,0.f), b1 = b0;
            if (ng < N) {
                const float* bp = Bm + (size_t)ng * K + kt + kc;
                b0 = *(const float4*)(bp);
                b1 = *(const float4*)(bp + 4);
            }
            Bs[kc + 0][nn] = b0.x; Bs[kc + 1][nn] = b0.y;
            Bs[kc + 2][nn] = b0.z; Bs[kc + 3][nn] = b0.w;
            Bs[kc + 4][nn] = b1.x; Bs[kc + 5][nn] = b1.y;
            Bs[kc + 6][nn] = b1.z; Bs[kc + 7][nn] = b1.w;
        } else {
            int kk = tid >> 4;           // 0..15
            int nn = (tid & 15) * 8;
            const float* bp = Bm + (size_t)(kt + kk) * N + bx * 128 + nn;
            *(float4*)&Bs[kk][nn]     = *(const float4*)(bp);
            *(float4*)&Bs[kk][nn + 4] = *(const float4*)(bp + 4);
        }
        __syncthreads();

#pragma unroll
        for (int k = 0; k < 16; k++) {
            float4 a0 = *(const float4*)&As[k][ty * 8];
            float4 a1 = *(const float4*)&As[k][ty * 8 + 4];
            float4 b0 = *(const float4*)&Bs[k][tx * 8];
            float4 b1 = *(const float4*)&Bs[k][tx * 8 + 4];
            float av[8] = {a0.x, a0.y, a0.z, a0.w, a1.x, a1.y, a1.z, a1.w};
            float bv[8] = {b0.x, b0.y, b0.z, b0.w, b1.x, b1.y, b1.z, b1.w};
#pragma unroll
            for (int i = 0; i < 8; i++)
#pragma unroll
                for (int j = 0; j < 8; j++)
                    acc[i][j] += av[i] * bv[j];
        }
        __syncthreads();
    }

#pragma unroll
    for (int i = 0; i < 8; i++) {
        float* crow = C + (size_t)(by * 128 + ty * 8 + i) * ldc + bx * 128 + tx * 8;
#pragma unroll
        for (int j = 0; j < 8; j++) {
            int col = bx * 128 + tx * 8 + j;
            if (col < N) crow[j] = acc[i][j] + bias[col];
        }
    }
}

// ---------------- per-instance normalization ----------------
__global__ void norm_kernel(const float* __restrict__ pts, int P, float* __restrict__ nrm)
{
    __shared__ float sx[128], sy[128];
    int n = blockIdx.x, tid = threadIdx.x;
    const float* base = pts + (size_t)n * P * 2;
    float ax = 0.f, ay = 0.f;
    for (int p = tid; p < P; p += 128) { ax += base[2 * p]; ay += base[2 * p + 1]; }
    sx[tid] = ax; sy[tid] = ay;
    __syncthreads();
    for (int s = 64; s > 0; s >>= 1) {
        if (tid < s) { sx[tid] += sx[tid + s]; sy[tid] += sy[tid + s]; }
        __syncthreads();
    }
    float mx = sx[0] / (float)P;
    float my = sy[0] / (float)P;
    __syncthreads();
    float am = 0.f;
    for (int p = tid; p < P; p += 128) {
        am = fmaxf(am, fmaxf(fabsf(base[2 * p] - mx), fabsf(base[2 * p + 1] - my)));
    }
    sx[tid] = am;
    __syncthreads();
    for (int s = 64; s > 0; s >>= 1) {
        if (tid < s) sx[tid] = fmaxf(sx[tid], sx[tid + s]);
        __syncthreads();
    }
    if (tid == 0) {
        nrm[n * 4]     = mx;
        nrm[n * 4 + 1] = my;
        nrm[n * 4 + 2] = 1.f / (sx[0] + 1e-6f);
    }
}

// ---------------- bilinear sample + token features ----------------
__global__ void sample_kernel(const float* __restrict__ feat, const float* __restrict__ pts,
                              const int* __restrict__ img_idx, const float* __restrict__ nrm,
                              float* __restrict__ xout, int P, int T)
{
    int warp = threadIdx.x >> 5;
    int lane = threadIdx.x & 31;
    int t = blockIdx.x * 8 + warp;
    if (t >= T) return;
    int n = t / P;
    float px = pts[t * 2], py = pts[t * 2 + 1];
    int img = img_idx[n];
    float ix = px - 0.5f, iy = py - 0.5f;
    float x0f = floorf(ix), y0f = floorf(iy);
    float wx = ix - x0f, wy = iy - y0f;
    int x0 = (int)x0f, y0 = (int)y0f;
    float w00 = (1.f - wx) * (1.f - wy);
    float w10 = wx * (1.f - wy);
    float w01 = (1.f - wx) * wy;
    float w11 = wx * wy;
    bool vx0 = (x0 >= 0 && x0 < WW), vx1 = (x0 + 1 >= 0 && x0 + 1 < WW);
    bool vy0 = (y0 >= 0 && y0 < HH), vy1 = (y0 + 1 >= 0 && y0 + 1 < HH);
    if (!(vx0 && vy0)) w00 = 0.f;
    if (!(vx1 && vy0)) w10 = 0.f;
    if (!(vx0 && vy1)) w01 = 0.f;
    if (!(vx1 && vy1)) w11 = 0.f;
    int xc0 = min(max(x0, 0), WW - 1), xc1 = min(max(x0 + 1, 0), WW - 1);
    int yc0 = min(max(y0, 0), HH - 1), yc1 = min(max(y0 + 1, 0), HH - 1);
    size_t b00 = (((size_t)img * HH + yc0) * WW + xc0) * FEATPAD;
    size_t b10 = (((size_t)img * HH + yc0) * WW + xc1) * FEATPAD;
    size_t b01 = (((size_t)img * HH + yc1) * WW + xc0) * FEATPAD;
    size_t b11 = (((size_t)img * HH + yc1) * WW + xc1) * FEATPAD;
    float* xr = xout + (size_t)t * DMODEL;
    for (int c = lane; c < FEATC; c += 32) {
        xr[c] = w00 * feat[b00 + c] + w10 * feat[b10 + c] +
                w01 * feat[b01 + c] + w11 * feat[b11 + c];
    }
    if (lane == 0) {
        float mx = nrm[n * 4], my = nrm[n * 4 + 1], inv = nrm[n * 4 + 2];
        xr[254] = (px - mx) * inv;
        xr[255] = (py - my) * inv;
    }
}

// ---------------- attention ----------------
__global__ void attn_kernel(const float* __restrict__ qkv, float* __restrict__ att, int P)
{
    __shared__ float4 k_s[P1 * 8];
    __shared__ float4 v_s[P1 * 8];
    int n = blockIdx.x, h = blockIdx.y;
    int tid = threadIdx.x;

    for (int i = tid; i < P * 8; i += 128) {
        int p = i >> 3, c = i & 7;
        const float* row = qkv + (size_t)(n * P + p) * 768 + h * 32;
        k_s[i] = ((const float4*)(row + 256))[c];
        v_s[i] = ((const float4*)(row + 512))[c];
    }
    __syncthreads();

    const float QS = 0.17677669529663689f * 1.44269504088896340f;
    for (int p = tid; p < P; p += 128) {
        const float4* qrow = (const float4*)(qkv + (size_t)(n * P + p) * 768 + h * 32);
        float q[32];
#pragma unroll
        for (int c = 0; c < 8; c++) {
            float4 tq = qrow[c];
            q[4 * c]     = tq.x * QS;
            q[4 * c + 1] = tq.y * QS;
            q[4 * c + 2] = tq.z * QS;
            q[4 * c + 3] = tq.w * QS;
        }
        float m = -INFINITY, l = 0.f;
        float o[32];
#pragma unroll
        for (int d = 0; d < 32; d++) o[d] = 0.f;

        for (int j = 0; j < P; j++) {
            const float* kr = (const float*)&k_s[j * 8];
            float s0 = 0.f, s1 = 0.f, s2 = 0.f, s3 = 0.f;
#pragma unroll
            for (int d = 0; d < 32; d += 4) {
                s0 += q[d] * kr[d];
                s1 += q[d + 1] * kr[d + 1];
                s2 += q[d + 2] * kr[d + 2];
                s3 += q[d + 3] * kr[d + 3];
            }
            float s = (s0 + s1) + (s2 + s3);
            if (s > m) {
                float corr = exp2f(m - s);
                m = s;
                l *= corr;
#pragma unroll
                for (int d = 0; d < 32; d++) o[d] *= corr;
            }
            float pw = exp2f(s - m);
            l += pw;
            const float* vr = (const float*)&v_s[j * 8];
#pragma unroll
            for (int d = 0; d < 32; d++) o[d] += pw * vr[d];
        }
        float inv = 1.f / l;
        float* orow = att + (size_t)(n * P + p) * 256 + h * 32;
#pragma unroll
        for (int d = 0; d < 32; d++) orow[d] = o[d] * inv;
    }
}

// ---------------- fused head ----------------
__global__ void head_kernel(const float* __restrict__ att, const float* __restrict__ wp,
                            const float* __restrict__ polyin, float* __restrict__ polyout,
                            float* __restrict__ outp, float strideF, int P, int stage1, int T)
{
    __shared__ float s_wp[514];
    for (int i = threadIdx.x; i < 514; i += 128) s_wp[i] = wp[i];
    __syncthreads();
    int warp = threadIdx.x >> 5;
    int lane = threadIdx.x & 31;
    int t = blockIdx.x * 4 + warp;
    if (t >= T) return;
    int n = t / P, p = t % P;
    const float* ar = att + (size_t)t * 256;
    float a0 = 0.f, a1 = 0.f;
    for (int c = lane; c < 256; c += 32) {
        float av = ar[c];
        a0 += av * s_wp[2 * c];
        a1 += av * s_wp[2 * c + 1];
    }
#pragma unroll
    for (int off = 16; off; off >>= 1) {
        a0 += __shfl_down_sync(0xffffffffu, a0, off);
        a1 += __shfl_down_sync(0xffffffffu, a1, off);
    }
    if (lane == 0) {
        if (stage1 && p == 0) return;
        int pidx = stage1 ? (n * NPOINT + p - 1) : (n * NPOINT + p);
        float ox = a0 + s_wp[512];
        float oy = a1 + s_wp[513];
        float rx = ox * strideF + polyin[pidx * 2];
        float ry = oy * strideF + polyin[pidx * 2 + 1];
        if (polyout) {
            polyout[pidx * 2]     = rx;
            polyout[pidx * 2 + 1] = ry;
        }
        outp[pidx * 2]     = rx * 4.0f;
        outp[pidx * 2 + 1] = ry * 4.0f;
    }
}

// ---------------- launch ----------------
extern "C" void kernel_launch(void* const* d_in, const int* in_sizes, int n_in,
                              void* d_out, int out_size)
{
    const float* cnn     = (const float*)d_in[0];
    const float* wh      = (const float*)d_in[1];
    const int*   ct_ind  = (const int*)  d_in[2];
    const int*   ct_img  = (const int*)  d_in[3];
    const float* f1_w1   = (const float*)d_in[4];
    const float* f1_b1   = (const float*)d_in[5];
    const float* f1_w2   = (const float*)d_in[6];
    const float* f1_b2   = (const float*)d_in[7];
    const float* f2_w1   = (const float*)d_in[8];
    const float* f2_b1   = (const float*)d_in[9];
    const float* f2_w2   = (const float*)d_in[10];
    const float* f2_b2   = (const float*)d_in[11];
    const float* c1_wqkv = (const float*)d_in[12];
    const float* c1_bqkv = (const float*)d_in[13];
    const float* c1_wo   = (const float*)d_in[14];
    const float* c1_bo   = (const float*)d_in[15];
    const float* c1_wh   = (const float*)d_in[16];
    const float* c1_bh   = (const float*)d_in[17];
    const float* c2_wqkv = (const float*)d_in[18];
    const float* c2_bqkv = (const float*)d_in[19];
    const float* c2_wo   = (const float*)d_in[20];
    const float* c2_bo   = (const float*)d_in[21];
    const float* c2_wh   = (const float*)d_in[22];
    const float* c2_bh   = (const float*)d_in[23];
    float* out = (float*)d_out;

    void *p_tmp, *p_feat1, *p_feat2, *p_pts1, *p_init, *p_coarse, *p_nrm;
    void *p_x, *p_qkv, *p_att, *p_wp1, *p_wp2;
    cudaGetSymbolAddress(&p_tmp, g_tmp);
    cudaGetSymbolAddress(&p_feat1, g_feat1);
    cudaGetSymbolAddress(&p_feat2, g_feat2);
    cudaGetSymbolAddress(&p_pts1, g_pts1);
    cudaGetSymbolAddress(&p_init, g_init);
    cudaGetSymbolAddress(&p_coarse, g_coarse);
    cudaGetSymbolAddress(&p_nrm, g_nrm);
    cudaGetSymbolAddress(&p_x, g_x);
    cudaGetSymbolAddress(&p_qkv, g_qkv);
    cudaGetSymbolAddress(&p_att, g_att);
    cudaGetSymbolAddress(&p_wp1, g_wp1);
    cudaGetSymbolAddress(&p_wp2, g_wp2);
    float* tmp    = (float*)p_tmp;
    float* feat1  = (float*)p_feat1;
    float* feat2  = (float*)p_feat2;
    float* pts1   = (float*)p_pts1;
    float* initp  = (float*)p_init;
    float* coarse = (float*)p_coarse;
    float* nrm    = (float*)p_nrm;
    float* xbuf   = (float*)p_x;
    float* qkv    = (float*)p_qkv;
    float* att    = (float*)p_att;
    float* wp1    = (float*)p_wp1;
    float* wp2    = (float*)p_wp2;

    fuse_head_kernel<<<1, 256>>>(c1_wo, c1_bo, c1_wh, c1_bh, wp1);
    fuse_head_kernel<<<1, 256>>>(c2_wo, c2_bo, c2_wh, c2_bh, wp2);

    init_kernel<<<NINST, 128>>>(wh, ct_ind, ct_img, pts1, initp, out);

    conv3x3_kernel<<<dim3(32, 8, 8), 256>>>(cnn, f1_w1, f1_b1, tmp);
    sgemm_kernel<true><<<dim3(2, PIX / 128), 256>>>(tmp, f1_w2, f1_b2, feat1,
                                                    PIX, FEATC, 256, FEATPAD);
    conv3x3_kernel<<<dim3(32, 8, 8), 256>>>(cnn, f2_w1, f2_b1, tmp);
    sgemm_kernel<true><<<dim3(2, PIX / 128), 256>>>(tmp, f2_w2, f2_b2, feat2,
                                                    PIX, FEATC, 256, FEATPAD);

    // ---- stage 1 ----
    norm_kernel<<<NINST, 128>>>(pts1, P1, nrm);
    sample_kernel<<<(T1 + 7) / 8, 256>>>(feat1, pts1, ct_img, nrm, xbuf, P1, T1);
    sgemm_kernel<false><<<dim3(6, T1 / 128), 256>>>(xbuf, c1_wqkv, c1_bqkv, qkv,
                                                    T1, 768, 256, 768);
    attn_kernel<<<dim3(NINST, 8), 128>>>(qkv, att, P1);
    head_kernel<<<(T1 + 3) / 4, 128>>>(att, wp1, initp, coarse,
                                       out + NINST * NPOINT * 2, 4.0f, P1, 1, T1);

    // ---- stage 2 ----
    norm_kernel<<<NINST, 128>>>(coarse, P2, nrm);
    sample_kernel<<<(T2 + 7) / 8, 256>>>(feat2, coarse, ct_img, nrm, xbuf, P2, T2);
    sgemm_kernel<false><<<dim3(6, T2 / 128), 256>>>(xbuf, c2_wqkv, c2_bqkv, qkv,
                                                    T2, 768, 256, 768);
    attn_kernel<<<dim3(NINST, 8), 128>>>(qkv, att, P2);
    head_kernel<<<(T2 + 3) / 4, 128>>>(att, wp2, coarse, nullptr,
                                       out + 2 * NINST * NPOINT * 2, 1.0f, P2, 0, T2);
}

// round 3
// speedup vs baseline: 1.3403x; 1.0019x over previous
#include <cuda_runtime.h>
#include <math.h>

// ---------------- problem constants ----------------
constexpr int BB      = 8;
constexpr int C_INC   = 64;
constexpr int HH      = 128;
constexpr int WW      = 128;
constexpr int NPOINT  = 128;
constexpr int NINST   = 512;
constexpr int DMODEL  = 256;
constexpr int P1      = 129;
constexpr int P2      = 128;
constexpr int FEATC   = 254;
constexpr int FEATPAD = 256;
constexpr int PIX     = BB * HH * WW;     // 131072
constexpr int T1      = NINST * P1;       // 66048
constexpr int T2      = NINST * P2;       // 65536

// ---------------- scratch ----------------
__device__ float g_tmp  [ (size_t)PIX * 256 ];
__device__ float g_feat1[ (size_t)PIX * FEATPAD ];
__device__ float g_feat2[ (size_t)PIX * FEATPAD ];
__device__ float g_pts1 [ NINST * P1 * 2 ];
__device__ float g_init [ NINST * NPOINT * 2 ];
__device__ float g_coarse[ NINST * NPOINT * 2 ];
__device__ float g_nrm  [ NINST * 4 ];
__device__ float g_x    [ (size_t)T1 * DMODEL ];
__device__ float g_qkv  [ (size_t)T1 * 3 * DMODEL ];
__device__ float g_att  [ (size_t)T1 * DMODEL ];
__device__ float g_wp1  [ 514 ];
__device__ float g_wp2  [ 514 ];

// ---------------- fused head weights ----------------
__global__ void fuse_head_kernel(const float* __restrict__ wo, const float* __restrict__ bo,
                                 const float* __restrict__ wh, const float* __restrict__ bh,
                                 float* __restrict__ wp)
{
    int c = threadIdx.x;
    float s0 = 0.f, s1 = 0.f;
    for (int k = 0; k < 256; k++) {
        float w = wo[c * 256 + k];
        s0 += w * wh[2 * k];
        s1 += w * wh[2 * k + 1];
    }
    wp[2 * c] = s0;
    wp[2 * c + 1] = s1;
    if (c == 0) {
        float b0 = bh[0], b1 = bh[1];
        for (int k = 0; k < 256; k++) {
            b0 += bo[k] * wh[2 * k];
            b1 += bo[k] * wh[2 * k + 1];
        }
        wp[512] = b0;
        wp[513] = b1;
    }
}

// ---------------- init ----------------
__global__ void init_kernel(const float* __restrict__ wh, const int* __restrict__ ct_ind,
                            const int* __restrict__ ct_img, float* __restrict__ pts1,
                            float* __restrict__ initp, float* __restrict__ out0)
{
    int n = blockIdx.x;
    int p = threadIdx.x;
    int ci = ct_ind[n];
    int cx = ci % WW;
    int cy = ci / WW;
    int img = ct_img[n];
    size_t base = (((size_t)img * 256 + 2 * p) * HH + cy) * WW + cx;
    float ox = wh[base];
    float oy = wh[base + (size_t)HH * WW];
    float fx = ox * 10.0f + (float)cx;
    float fy = oy * 10.0f + (float)cy;
    pts1[(n * P1 + 1 + p) * 2]     = fx;
    pts1[(n * P1 + 1 + p) * 2 + 1] = fy;
    if (p == 0) {
        pts1[n * P1 * 2]     = (float)cx;
        pts1[n * P1 * 2 + 1] = (float)cy;
    }
    int pidx = n * NPOINT + p;
    initp[pidx * 2]     = fx;
    initp[pidx * 2 + 1] = fy;
    out0[pidx * 2]     = fx * 4.0f;
    out0[pidx * 2 + 1] = fy * 4.0f;
}

// ---------------- conv3x3: NCHW->NHWC, pad 1, bias+relu ----------------
// 256 threads; tile 16y x 32x; each thread: 2 pixels (y, y+8) x 32 oc.
// s_w row stride 36 floats = 144B (16B aligned) -> LDS.128 broadcast reads.
__global__ __launch_bounds__(256, 2)
void conv3x3_kernel(const float* __restrict__ in, const float* __restrict__ w,
                    const float* __restrict__ bias, float* __restrict__ out)
{
    __shared__ __align__(16) float s_in[8 * 18 * 36];   // [cin][yy(18)][xx stride 36]
    __shared__ __align__(16) float s_w[72 * 36];        // [q = cin*9+tap][oc], stride 36

    int tid = threadIdx.x;
    int ty = tid >> 5;          // 0..7
    int tx = tid & 31;          // 0..31
    int ytile = blockIdx.x >> 2;   // 0..7
    int xtile = blockIdx.x & 3;    // 0..3
    int y0 = ytile * 16;
    int x0 = xtile * 32;
    int ocb = blockIdx.y;       // 0..7
    int b   = blockIdx.z;

    float acc0[32], acc1[32];
#pragma unroll
    for (int oc = 0; oc < 32; oc++) { acc0[oc] = 0.f; acc1[oc] = 0.f; }

    for (int cb = 0; cb < C_INC; cb += 8) {
        // input patch: 8 cin x 18 rows x 34 cols (zero-padded)
        for (int i = tid; i < 8 * 18 * 34; i += 256) {
            int c  = i / 612;
            int r  = i % 612;
            int yy = r / 34;
            int xx = r % 34;
            int gy = y0 + yy - 1;
            int gx = x0 + xx - 1;
            float v = 0.f;
            if (gy >= 0 && gy < HH && gx >= 0 && gx < WW)
                v = in[(((size_t)b * C_INC + cb + c) * HH + gy) * WW + gx];
            s_in[c * 648 + yy * 36 + xx] = v;
        }
        // weights: 32 oc x 72 q
        for (int i = tid; i < 32 * 72; i += 256) {
            int oc = i / 72;
            int q  = i % 72;
            s_w[q * 36 + oc] = w[(size_t)(ocb * 32 + oc) * 576 + cb * 9 + q];
        }
        __syncthreads();

        for (int cin = 0; cin < 8; cin++) {
#pragma unroll
            for (int ky = 0; ky < 3; ky++) {
#pragma unroll
                for (int kx = 0; kx < 3; kx++) {
                    float v0 = s_in[cin * 648 + (ty + ky) * 36 + (tx + kx)];
                    float v1 = s_in[cin * 648 + (ty + 8 + ky) * 36 + (tx + kx)];
                    const float4* w4 = (const float4*)&s_w[(cin * 9 + ky * 3 + kx) * 36];
#pragma unroll
                    for (int j = 0; j < 8; j++) {
                        float4 wv = w4[j];
                        acc0[4 * j]     += v0 * wv.x;
                        acc0[4 * j + 1] += v0 * wv.y;
                        acc0[4 * j + 2] += v0 * wv.z;
                        acc0[4 * j + 3] += v0 * wv.w;
                        acc1[4 * j]     += v1 * wv.x;
                        acc1[4 * j + 1] += v1 * wv.y;
                        acc1[4 * j + 2] += v1 * wv.z;
                        acc1[4 * j + 3] += v1 * wv.w;
                    }
                }
            }
        }
        __syncthreads();
    }

    int x = x0 + tx;
    size_t ob0 = (((size_t)b * HH + (y0 + ty)) * WW + x) * 256 + ocb * 32;
    size_t ob1 = (((size_t)b * HH + (y0 + ty + 8)) * WW + x) * 256 + ocb * 32;
#pragma unroll
    for (int oc = 0; oc < 32; oc++) {
        float bv = bias[ocb * 32 + oc];
        out[ob0 + oc] = fmaxf(acc0[oc] + bv, 0.f);
        out[ob1 + oc] = fmaxf(acc1[oc] + bv, 0.f);
    }
}

// ---------------- SGEMM: C[MxN] = A[MxK] * B (+bias) ----------------
// 128x128 tile, BK=16, 256 threads, 8x8 microtile. M%128==0, K%16==0.
// TB=false: B is [K][N] row-major, N%8==0. TB=true: B is [N][K] (1x1 conv weights).
template <bool TB>
__global__ __launch_bounds__(256, 2)
void sgemm_kernel(const float* __restrict__ A, const float* __restrict__ Bm,
                  const float* __restrict__ bias, float* __restrict__ C,
                  int M, int N, int K, int ldc)
{
    __shared__ __align__(16) float As[16][132];
    __shared__ __align__(16) float Bs[16][132];

    int tid = threadIdx.x;
    int tx = tid & 15;
    int ty = tid >> 4;
    int bx = blockIdx.x;
    int by = blockIdx.y;

    float acc[8][8];
#pragma unroll
    for (int i = 0; i < 8; i++)
#pragma unroll
        for (int j = 0; j < 8; j++) acc[i][j] = 0.f;

    int ar = tid >> 1;            // 0..127
    int ac = (tid & 1) * 8;       // 0 or 8

    for (int kt = 0; kt < K; kt += 16) {
        // A tile: 128 rows x 16 k  (transpose into As[k][m])
        {
            const float* ap = A + (size_t)(by * 128 + ar) * K + kt + ac;
            float4 a0 = *(const float4*)(ap);
            float4 a1 = *(const float4*)(ap + 4);
            As[ac + 0][ar] = a0.x; As[ac + 1][ar] = a0.y;
            As[ac + 2][ar] = a0.z; As[ac + 3][ar] = a0.w;
            As[ac + 4][ar] = a1.x; As[ac + 5][ar] = a1.y;
            As[ac + 6][ar] = a1.z; As[ac + 7][ar] = a1.w;
        }
        if (TB) {
            int nn = tid >> 1;          // 0..127
            int kc = (tid & 1) * 8;
            int ng = bx * 128 + nn;
            float4 b0 = make_float4(0.f,0.f,0.f,0.f), b1 = b0;
            if (ng < N) {
                const float* bp = Bm + (size_t)ng * K + kt + kc;
                b0 = *(const float4*)(bp);
                b1 = *(const float4*)(bp + 4);
            }
            Bs[kc + 0][nn] = b0.x; Bs[kc + 1][nn] = b0.y;
            Bs[kc + 2][nn] = b0.z; Bs[kc + 3][nn] = b0.w;
            Bs[kc + 4][nn] = b1.x; Bs[kc + 5][nn] = b1.y;
            Bs[kc + 6][nn] = b1.z; Bs[kc + 7][nn] = b1.w;
        } else {
            int kk = tid >> 4;           // 0..15
            int nn = (tid & 15) * 8;
            const float* bp = Bm + (size_t)(kt + kk) * N + bx * 128 + nn;
            *(float4*)&Bs[kk][nn]     = *(const float4*)(bp);
            *(float4*)&Bs[kk][nn + 4] = *(const float4*)(bp + 4);
        }
        __syncthreads();

#pragma unroll
        for (int k = 0; k < 16; k++) {
            float4 a0 = *(const float4*)&As[k][ty * 8];
            float4 a1 = *(const float4*)&As[k][ty * 8 + 4];
            float4 b0 = *(const float4*)&Bs[k][tx * 8];
            float4 b1 = *(const float4*)&Bs[k][tx * 8 + 4];
            float av[8] = {a0.x, a0.y, a0.z, a0.w, a1.x, a1.y, a1.z, a1.w};
            float bv[8] = {b0.x, b0.y, b0.z, b0.w, b1.x, b1.y, b1.z, b1.w};
#pragma unroll
            for (int i = 0; i < 8; i++)
#pragma unroll
                for (int j = 0; j < 8; j++)
                    acc[i][j] += av[i] * bv[j];
        }
        __syncthreads();
    }

#pragma unroll
    for (int i = 0; i < 8; i++) {
        float* crow = C + (size_t)(by * 128 + ty * 8 + i) * ldc + bx * 128 + tx * 8;
#pragma unroll
        for (int j = 0; j < 8; j++) {
            int col = bx * 128 + tx * 8 + j;
            if (col < N) crow[j] = acc[i][j] + bias[col];
        }
    }
}

// ---------------- per-instance normalization ----------------
__global__ void norm_kernel(const float* __restrict__ pts, int P, float* __restrict__ nrm)
{
    __shared__ float sx[128], sy[128];
    int n = blockIdx.x, tid = threadIdx.x;
    const float* base = pts + (size_t)n * P * 2;
    float ax = 0.f, ay = 0.f;
    for (int p = tid; p < P; p += 128) { ax += base[2 * p]; ay += base[2 * p + 1]; }
    sx[tid] = ax; sy[tid] = ay;
    __syncthreads();
    for (int s = 64; s > 0; s >>= 1) {
        if (tid < s) { sx[tid] += sx[tid + s]; sy[tid] += sy[tid + s]; }
        __syncthreads();
    }
    float mx = sx[0] / (float)P;
    float my = sy[0] / (float)P;
    __syncthreads();
    float am = 0.f;
    for (int p = tid; p < P; p += 128) {
        am = fmaxf(am, fmaxf(fabsf(base[2 * p] - mx), fabsf(base[2 * p + 1] - my)));
    }
    sx[tid] = am;
    __syncthreads();
    for (int s = 64; s > 0; s >>= 1) {
        if (tid < s) sx[tid] = fmaxf(sx[tid], sx[tid + s]);
        __syncthreads();
    }
    if (tid == 0) {
        nrm[n * 4]     = mx;
        nrm[n * 4 + 1] = my;
        nrm[n * 4 + 2] = 1.f / (sx[0] + 1e-6f);
    }
}

// ---------------- bilinear sample + token features ----------------
__global__ void sample_kernel(const float* __restrict__ feat, const float* __restrict__ pts,
                              const int* __restrict__ img_idx, const float* __restrict__ nrm,
                              float* __restrict__ xout, int P, int T)
{
    int warp = threadIdx.x >> 5;
    int lane = threadIdx.x & 31;
    int t = blockIdx.x * 8 + warp;
    if (t >= T) return;
    int n = t / P;
    float px = pts[t * 2], py = pts[t * 2 + 1];
    int img = img_idx[n];
    float ix = px - 0.5f, iy = py - 0.5f;
    float x0f = floorf(ix), y0f = floorf(iy);
    float wx = ix - x0f, wy = iy - y0f;
    int x0 = (int)x0f, y0 = (int)y0f;
    float w00 = (1.f - wx) * (1.f - wy);
    float w10 = wx * (1.f - wy);
    float w01 = (1.f - wx) * wy;
    float w11 = wx * wy;
    bool vx0 = (x0 >= 0 && x0 < WW), vx1 = (x0 + 1 >= 0 && x0 + 1 < WW);
    bool vy0 = (y0 >= 0 && y0 < HH), vy1 = (y0 + 1 >= 0 && y0 + 1 < HH);
    if (!(vx0 && vy0)) w00 = 0.f;
    if (!(vx1 && vy0)) w10 = 0.f;
    if (!(vx0 && vy1)) w01 = 0.f;
    if (!(vx1 && vy1)) w11 = 0.f;
    int xc0 = min(max(x0, 0), WW - 1), xc1 = min(max(x0 + 1, 0), WW - 1);
    int yc0 = min(max(y0, 0), HH - 1), yc1 = min(max(y0 + 1, 0), HH - 1);
    size_t b00 = (((size_t)img * HH + yc0) * WW + xc0) * FEATPAD;
    size_t b10 = (((size_t)img * HH + yc0) * WW + xc1) * FEATPAD;
    size_t b01 = (((size_t)img * HH + yc1) * WW + xc0) * FEATPAD;
    size_t b11 = (((size_t)img * HH + yc1) * WW + xc1) * FEATPAD;
    float* xr = xout + (size_t)t * DMODEL;
    for (int c = lane; c < FEATC; c += 32) {
        xr[c] = w00 * feat[b00 + c] + w10 * feat[b10 + c] +
                w01 * feat[b01 + c] + w11 * feat[b11 + c];
    }
    if (lane == 0) {
        float mx = nrm[n * 4], my = nrm[n * 4 + 1], inv = nrm[n * 4 + 2];
        xr[254] = (px - mx) * inv;
        xr[255] = (py - my) * inv;
    }
}

// ---------------- attention ----------------
__global__ void attn_kernel(const float* __restrict__ qkv, float* __restrict__ att, int P)
{
    __shared__ float4 k_s[P1 * 8];
    __shared__ float4 v_s[P1 * 8];
    int n = blockIdx.x, h = blockIdx.y;
    int tid = threadIdx.x;

    for (int i = tid; i < P * 8; i += 128) {
        int p = i >> 3, c = i & 7;
        const float* row = qkv + (size_t)(n * P + p) * 768 + h * 32;
        k_s[i] = ((const float4*)(row + 256))[c];
        v_s[i] = ((const float4*)(row + 512))[c];
    }
    __syncthreads();

    const float QS = 0.17677669529663689f * 1.44269504088896340f;
    for (int p = tid; p < P; p += 128) {
        const float4* qrow = (const float4*)(qkv + (size_t)(n * P + p) * 768 + h * 32);
        float q[32];
#pragma unroll
        for (int c = 0; c < 8; c++) {
            float4 tq = qrow[c];
            q[4 * c]     = tq.x * QS;
            q[4 * c + 1] = tq.y * QS;
            q[4 * c + 2] = tq.z * QS;
            q[4 * c + 3] = tq.w * QS;
        }
        float m = -INFINITY, l = 0.f;
        float o[32];
#pragma unroll
        for (int d = 0; d < 32; d++) o[d] = 0.f;

        for (int j = 0; j < P; j++) {
            const float* kr = (const float*)&k_s[j * 8];
            float s0 = 0.f, s1 = 0.f, s2 = 0.f, s3 = 0.f;
#pragma unroll
            for (int d = 0; d < 32; d += 4) {
                s0 += q[d] * kr[d];
                s1 += q[d + 1] * kr[d + 1];
                s2 += q[d + 2] * kr[d + 2];
                s3 += q[d + 3] * kr[d + 3];
            }
            float s = (s0 + s1) + (s2 + s3);
            if (s > m) {
                float corr = exp2f(m - s);
                m = s;
                l *= corr;
#pragma unroll
                for (int d = 0; d < 32; d++) o[d] *= corr;
            }
            float pw = exp2f(s - m);
            l += pw;
            const float* vr = (const float*)&v_s[j * 8];
#pragma unroll
            for (int d = 0; d < 32; d++) o[d] += pw * vr[d];
        }
        float inv = 1.f / l;
        float* orow = att + (size_t)(n * P + p) * 256 + h * 32;
#pragma unroll
        for (int d = 0; d < 32; d++) orow[d] = o[d] * inv;
    }
}

// ---------------- fused head ----------------
__global__ void head_kernel(const float* __restrict__ att, const float* __restrict__ wp,
                            const float* __restrict__ polyin, float* __restrict__ polyout,
                            float* __restrict__ outp, float strideF, int P, int stage1, int T)
{
    __shared__ float s_wp[514];
    for (int i = threadIdx.x; i < 514; i += 128) s_wp[i] = wp[i];
    __syncthreads();
    int warp = threadIdx.x >> 5;
    int lane = threadIdx.x & 31;
    int t = blockIdx.x * 4 + warp;
    if (t >= T) return;
    int n = t / P, p = t % P;
    const float* ar = att + (size_t)t * 256;
    float a0 = 0.f, a1 = 0.f;
    for (int c = lane; c < 256; c += 32) {
        float av = ar[c];
        a0 += av * s_wp[2 * c];
        a1 += av * s_wp[2 * c + 1];
    }
#pragma unroll
    for (int off = 16; off; off >>= 1) {
        a0 += __shfl_down_sync(0xffffffffu, a0, off);
        a1 += __shfl_down_sync(0xffffffffu, a1, off);
    }
    if (lane == 0) {
        if (stage1 && p == 0) return;
        int pidx = stage1 ? (n * NPOINT + p - 1) : (n * NPOINT + p);
        float ox = a0 + s_wp[512];
        float oy = a1 + s_wp[513];
        float rx = ox * strideF + polyin[pidx * 2];
        float ry = oy * strideF + polyin[pidx * 2 + 1];
        if (polyout) {
            polyout[pidx * 2]     = rx;
            polyout[pidx * 2 + 1] = ry;
        }
        outp[pidx * 2]     = rx * 4.0f;
        outp[pidx * 2 + 1] = ry * 4.0f;
    }
}

// ---------------- launch ----------------
extern "C" void kernel_launch(void* const* d_in, const int* in_sizes, int n_in,
                              void* d_out, int out_size)
{
    const float* cnn     = (const float*)d_in[0];
    const float* wh      = (const float*)d_in[1];
    const int*   ct_ind  = (const int*)  d_in[2];
    const int*   ct_img  = (const int*)  d_in[3];
    const float* f1_w1   = (const float*)d_in[4];
    const float* f1_b1   = (const float*)d_in[5];
    const float* f1_w2   = (const float*)d_in[6];
    const float* f1_b2   = (const float*)d_in[7];
    const float* f2_w1   = (const float*)d_in[8];
    const float* f2_b1   = (const float*)d_in[9];
    const float* f2_w2   = (const float*)d_in[10];
    const float* f2_b2   = (const float*)d_in[11];
    const float* c1_wqkv = (const float*)d_in[12];
    const float* c1_bqkv = (const float*)d_in[13];
    const float* c1_wo   = (const float*)d_in[14];
    const float* c1_bo   = (const float*)d_in[15];
    const float* c1_wh   = (const float*)d_in[16];
    const float* c1_bh   = (const float*)d_in[17];
    const float* c2_wqkv = (const float*)d_in[18];
    const float* c2_bqkv = (const float*)d_in[19];
    const float* c2_wo   = (const float*)d_in[20];
    const float* c2_bo   = (const float*)d_in[21];
    const float* c2_wh   = (const float*)d_in[22];
    const float* c2_bh   = (const float*)d_in[23];
    float* out = (float*)d_out;

    void *p_tmp, *p_feat1, *p_feat2, *p_pts1, *p_init, *p_coarse, *p_nrm;
    void *p_x, *p_qkv, *p_att, *p_wp1, *p_wp2;
    cudaGetSymbolAddress(&p_tmp, g_tmp);
    cudaGetSymbolAddress(&p_feat1, g_feat1);
    cudaGetSymbolAddress(&p_feat2, g_feat2);
    cudaGetSymbolAddress(&p_pts1, g_pts1);
    cudaGetSymbolAddress(&p_init, g_init);
    cudaGetSymbolAddress(&p_coarse, g_coarse);
    cudaGetSymbolAddress(&p_nrm, g_nrm);
    cudaGetSymbolAddress(&p_x, g_x);
    cudaGetSymbolAddress(&p_qkv, g_qkv);
    cudaGetSymbolAddress(&p_att, g_att);
    cudaGetSymbolAddress(&p_wp1, g_wp1);
    cudaGetSymbolAddress(&p_wp2, g_wp2);
    float* tmp    = (float*)p_tmp;
    float* feat1  = (float*)p_feat1;
    float* feat2  = (float*)p_feat2;
    float* pts1   = (float*)p_pts1;
    float* initp  = (float*)p_init;
    float* coarse = (float*)p_coarse;
    float* nrm    = (float*)p_nrm;
    float* xbuf   = (float*)p_x;
    float* qkv    = (float*)p_qkv;
    float* att    = (float*)p_att;
    float* wp1    = (float*)p_wp1;
    float* wp2    = (float*)p_wp2;

    fuse_head_kernel<<<1, 256>>>(c1_wo, c1_bo, c1_wh, c1_bh, wp1);
    fuse_head_kernel<<<1, 256>>>(c2_wo, c2_bo, c2_wh, c2_bh, wp2);

    init_kernel<<<NINST, 128>>>(wh, ct_ind, ct_img, pts1, initp, out);

    conv3x3_kernel<<<dim3(32, 8, 8), 256>>>(cnn, f1_w1, f1_b1, tmp);
    sgemm_kernel<true><<<dim3(2, PIX / 128), 256>>>(tmp, f1_w2, f1_b2, feat1,
                                                    PIX, FEATC, 256, FEATPAD);
    conv3x3_kernel<<<dim3(32, 8, 8), 256>>>(cnn, f2_w1, f2_b1, tmp);
    sgemm_kernel<true><<<dim3(2, PIX / 128), 256>>>(tmp, f2_w2, f2_b2, feat2,
                                                    PIX, FEATC, 256, FEATPAD);

    // ---- stage 1 ----
    norm_kernel<<<NINST, 128>>>(pts1, P1, nrm);
    sample_kernel<<<(T1 + 7) / 8, 256>>>(feat1, pts1, ct_img, nrm, xbuf, P1, T1);
    sgemm_kernel<false><<<dim3(6, T1 / 128), 256>>>(xbuf, c1_wqkv, c1_bqkv, qkv,
                                                    T1, 768, 256, 768);
    attn_kernel<<<dim3(NINST, 8), 128>>>(qkv, att, P1);
    head_kernel<<<(T1 + 3) / 4, 128>>>(att, wp1, initp, coarse,
                                       out + NINST * NPOINT * 2, 4.0f, P1, 1, T1);

    // ---- stage 2 ----
    norm_kernel<<<NINST, 128>>>(coarse, P2, nrm);
    sample_kernel<<<(T2 + 7) / 8, 256>>>(feat2, coarse, ct_img, nrm, xbuf, P2, T2);
    sgemm_kernel<false><<<dim3(6, T2 / 128), 256>>>(xbuf, c2_wqkv, c2_bqkv, qkv,
                                                    T2, 768, 256, 768);
    attn_kernel<<<dim3(NINST, 8), 128>>>(qkv, att, P2);
    head_kernel<<<(T2 + 3) / 4, 128>>>(att, wp2, coarse, nullptr,
                                       out + 2 * NINST * NPOINT * 2, 1.0f, P2, 0, T2);
}

// round 4
// speedup vs baseline: 2.9237x; 2.1814x over previous
#include <cuda_runtime.h>
#include <math.h>
#include <stdint.h>

constexpr int BB=8, C_INC=64, HH=128, WW=128, NPOINT=128, NINST=512, DMODEL=256;
constexpr int P1=129, P2=128, FEATC=254, FEATPAD=256;
constexpr int PIX=BB*HH*WW, T1=NINST*P1, T2=NINST*P2;

__device__ __align__(256) float g_int [(size_t)PIX*64];
__device__ __align__(256) float g_tmp [(size_t)PIX*256];
__device__ __align__(256) float g_feat1[(size_t)PIX*FEATPAD];
__device__ __align__(256) float g_feat2[(size_t)PIX*FEATPAD];
__device__ float g_pts1[NINST*P1*2];
__device__ float g_init[NINST*NPOINT*2];
__device__ float g_coarse[NINST*NPOINT*2];
__device__ float g_nrm[NINST*4];
__device__ __align__(256) float g_x  [(size_t)T1*DMODEL];
__device__ __align__(256) float g_qkv[(size_t)T1*3*DMODEL];
__device__ __align__(256) float g_att[(size_t)T1*DMODEL];
__device__ __align__(256) float g_wt [576*256];
__device__ __align__(256) float g_w2t[256*256];
__device__ __align__(256) float g_b2p[256];
__device__ __align__(256) float g_wq [256*768];
__device__ float g_wp1[514];
__device__ float g_wp2[514];

__device__ __forceinline__ float tf32r(float x){
    uint32_t u; asm("cvt.rna.tf32.f32 %0, %1;":"=r"(u):"f"(x)); return __uint_as_float(u);
}
__device__ __forceinline__ uint32_t smem_u32(const void* p){ return (uint32_t)__cvta_generic_to_shared(p); }
__device__ __forceinline__ void cpa16(uint32_t dst, const void* src){
    asm volatile("cp.async.ca.shared.global [%0], [%1], 16;"::"r"(dst),"l"(src));
}
#define CP_COMMIT() asm volatile("cp.async.commit_group;")
#define CP_WAIT1()  asm volatile("cp.async.wait_group 1;")
#define MMA8(d0,d1,d2,d3,a0,a1,a2,a3,b0,b1) \
    asm volatile("mma.sync.aligned.m16n8k8.row.col.f32.tf32.tf32.f32 " \
        "{%0,%1,%2,%3},{%4,%5,%6,%7},{%8,%9},{%0,%1,%2,%3};" \
        : "+f"(d0),"+f"(d1),"+f"(d2),"+f"(d3) \
        : "r"(a0),"r"(a1),"r"(a2),"r"(a3),"r"(b0),"r"(b1))

// ---------- prep ----------
__global__ void fuse_head_kernel(const float* __restrict__ wo, const float* __restrict__ bo,
                                 const float* __restrict__ wh, const float* __restrict__ bh,
                                 float* __restrict__ wp)
{
    int c = threadIdx.x;
    float s0=0.f, s1=0.f;
    for (int k=0;k<256;k++){ float w=wo[c*256+k]; s0+=w*wh[2*k]; s1+=w*wh[2*k+1]; }
    wp[2*c]=s0; wp[2*c+1]=s1;
    if (c==0){
        float b0=bh[0], b1=bh[1];
        for (int k=0;k<256;k++){ b0+=bo[k]*wh[2*k]; b1+=bo[k]*wh[2*k+1]; }
        wp[512]=b0; wp[513]=b1;
    }
}

__global__ void transpose_kernel(const float* __restrict__ in, float* __restrict__ out)
{
    __shared__ float s[64*129];
    int bid=blockIdx.x, b=bid>>7, y=bid&127;
    for (int i=threadIdx.x;i<8192;i+=256){
        int c=i>>7, x=i&127;
        s[c*129+x]=in[(((size_t)b*64+c)*128+y)*128+x];
    }
    __syncthreads();
    float* dst=out+(size_t)bid*8192;
    for (int i=threadIdx.x;i<8192;i+=256){
        int x=i>>6, c=i&63;
        dst[i]=tf32r(s[c*129+x]);
    }
}

__global__ void prep_wt_kernel(const float* __restrict__ w, float* __restrict__ wt)
{
    int q=blockIdx.x, t=q>>6, c=q&63, oc=threadIdx.x;
    wt[(size_t)q*256+oc]=tf32r(w[(size_t)oc*576+c*9+t]);
}

__global__ void prep_w2_kernel(const float* __restrict__ w2, const float* __restrict__ b2,
                               float* __restrict__ bt, float* __restrict__ bp)
{
    int k=blockIdx.x, n=threadIdx.x;
    bt[k*256+n]=(n<254)?tf32r(w2[(size_t)n*256+k]):0.f;
    if (k==0) bp[n]=(n<254)?b2[n]:0.f;
}

__global__ void prep_wq_kernel(const float* __restrict__ in, float* __restrict__ out)
{
    int i=blockIdx.x*256+threadIdx.x;
    float4 v=((const float4*)in)[i];
    v.x=tf32r(v.x); v.y=tf32r(v.y); v.z=tf32r(v.z); v.w=tf32r(v.w);
    ((float4*)out)[i]=v;
}

__global__ void init_kernel(const float* __restrict__ wh, const int* __restrict__ ct_ind,
                            const int* __restrict__ ct_img, float* __restrict__ pts1,
                            float* __restrict__ initp, float* __restrict__ out0)
{
    int n=blockIdx.x, p=threadIdx.x;
    int ci=ct_ind[n], cx=ci%WW, cy=ci/WW, img=ct_img[n];
    size_t base=(((size_t)img*256+2*p)*HH+cy)*WW+cx;
    float ox=wh[base], oy=wh[base+(size_t)HH*WW];
    float fx=ox*10.0f+(float)cx, fy=oy*10.0f+(float)cy;
    pts1[(n*P1+1+p)*2]=fx; pts1[(n*P1+1+p)*2+1]=fy;
    if (p==0){ pts1[n*P1*2]=(float)cx; pts1[n*P1*2+1]=(float)cy; }
    int pidx=n*NPOINT+p;
    initp[pidx*2]=fx; initp[pidx*2+1]=fy;
    out0[pidx*2]=fx*4.0f; out0[pidx*2+1]=fy*4.0f;
}

// ---------- conv3x3 implicit GEMM (tf32 mma) ----------
// block: 128 pixels (8y x 16x) x 128 oc; 256 threads = 8 warps (2M x 4N)
__global__ __launch_bounds__(256)
void conv3_tf32(const float* __restrict__ in_t, const float* __restrict__ wt,
                const float* __restrict__ bias, float* __restrict__ out)
{
    extern __shared__ float sm[];
    float* s_in=sm;                  // 180*68
    float* s_w =sm+180*68;           // 3*16*136

    int tid=threadIdx.x, warp=tid>>5, lane=tid&31;
    int g=lane>>2, l4=lane&3;
    int warpM=warp>>2, warpN=warp&3;
    int b=blockIdx.x>>7, rem=blockIdx.x&127;
    int y0=(rem>>3)*8, x0=(rem&7)*16;
    int ocb=blockIdx.y;

    auto loadB=[&](int ch,int stage){
        int t=ch>>2, cc=ch&3;
        const float* src=wt+((size_t)(t*64+cc*16))*256+ocb*128;
        float* dst=s_w+stage*(16*136);
#pragma unroll
        for (int j=0;j<2;j++){
            int q=tid+j*256, k=q>>5, seg=q&31;
            cpa16(smem_u32(dst+k*136+seg*4), src+(size_t)k*256+seg*4);
        }
    };
    loadB(0,0); CP_COMMIT();
    loadB(1,1); CP_COMMIT();

    for (int i=tid;i<180*16;i+=256){
        int ps=i>>4, seg=i&15;
        int r=ps/18, c=ps%18;
        int gy=y0+r-1, gx=x0+c-1;
        float4 v=make_float4(0.f,0.f,0.f,0.f);
        if (gy>=0&&gy<128&&gx>=0&&gx<128)
            v=*(const float4*)(in_t+(((size_t)(b*128+gy))*128+gx)*64+seg*4);
        *(float4*)(s_in+ps*68+seg*4)=v;
    }

    float acc[4][4][4];
#pragma unroll
    for (int mi=0;mi<4;mi++)
#pragma unroll
        for (int ni=0;ni<4;ni++)
#pragma unroll
            for (int r=0;r<4;r++) acc[mi][ni][r]=0.f;

    for (int ch=0;ch<36;ch++){
        CP_WAIT1();
        __syncthreads();
        if (ch+2<36) loadB(ch+2,(ch+2)%3);
        CP_COMMIT();

        int t=ch>>2, cc=ch&3, ky=t/3, kx=t%3;
        const uint32_t* su=(const uint32_t*)s_in;
        const uint32_t* bu=(const uint32_t*)(s_w+(ch%3)*(16*136));
#pragma unroll
        for (int k8=0;k8<16;k8+=8){
            uint32_t a[4][4];
#pragma unroll
            for (int mi=0;mi<4;mi++){
                int py=warpM*4+mi;
                int r0=((py+ky)*18+(g+kx))*68+cc*16+k8+l4;
                int r1=((py+ky)*18+(g+8+kx))*68+cc*16+k8+l4;
                a[mi][0]=su[r0]; a[mi][1]=su[r1]; a[mi][2]=su[r0+4]; a[mi][3]=su[r1+4];
            }
            uint32_t bf[4][2];
#pragma unroll
            for (int ni=0;ni<4;ni++){
                int col=warpN*32+ni*8+g;
                bf[ni][0]=bu[(k8+l4)*136+col];
                bf[ni][1]=bu[(k8+4+l4)*136+col];
            }
#pragma unroll
            for (int mi=0;mi<4;mi++)
#pragma unroll
                for (int ni=0;ni<4;ni++)
                    MMA8(acc[mi][ni][0],acc[mi][ni][1],acc[mi][ni][2],acc[mi][ni][3],
                         a[mi][0],a[mi][1],a[mi][2],a[mi][3],bf[ni][0],bf[ni][1]);
        }
        __syncthreads();
    }

#pragma unroll
    for (int mi=0;mi<4;mi++){
        int y=y0+warpM*4+mi;
#pragma unroll
        for (int ni=0;ni<4;ni++){
            int oc=ocb*128+warpN*32+ni*8+l4*2;
            float b0=bias[oc], b1=bias[oc+1];
            int x=x0+g;
            size_t p0=(((size_t)(b*128+y))*128+x)*256+oc;
            float2 r0,r1;
            r0.x=tf32r(fmaxf(acc[mi][ni][0]+b0,0.f));
            r0.y=tf32r(fmaxf(acc[mi][ni][1]+b1,0.f));
            r1.x=tf32r(fmaxf(acc[mi][ni][2]+b0,0.f));
            r1.y=tf32r(fmaxf(acc[mi][ni][3]+b1,0.f));
            *(float2*)(out+p0)=r0;
            *(float2*)(out+p0+8*256)=r1;
        }
    }
}

// ---------- generic tf32 GEMM: C = A[MxK]*B[KxN] + bias ----------
template <bool ROUND>
__global__ __launch_bounds__(256)
void gemm_tf32(const float* __restrict__ A, const float* __restrict__ B,
               const float* __restrict__ bias, float* __restrict__ C,
               int M, int N, int K)
{
    extern __shared__ float sm[];
    float* As=sm;                 // 3 x [128][20]
    float* Bs=sm+3*128*20;        // 3 x [16][136]

    int tid=threadIdx.x, warp=tid>>5, lane=tid&31;
    int g=lane>>2, l4=lane&3;
    int warpM=warp>>2, warpN=warp&3;
    int bx=blockIdx.x, by=blockIdx.y;
    int nk=K>>4;

    auto loadT=[&](int ch,int stage){
        int kt=ch<<4;
        float* ad=As+stage*(128*20);
        float* bd=Bs+stage*(16*136);
#pragma unroll
        for (int j=0;j<2;j++){
            int q=tid+j*256, row=q>>2, seg=q&3;
            cpa16(smem_u32(ad+row*20+seg*4), A+(size_t)(by*128+row)*K+kt+seg*4);
        }
#pragma unroll
        for (int j=0;j<2;j++){
            int q=tid+j*256, k=q>>5, seg=q&31;
            cpa16(smem_u32(bd+k*136+seg*4), B+(size_t)(kt+k)*N+bx*128+seg*4);
        }
    };

    float acc[4][4][4];
#pragma unroll
    for (int mi=0;mi<4;mi++)
#pragma unroll
        for (int ni=0;ni<4;ni++)
#pragma unroll
            for (int r=0;r<4;r++) acc[mi][ni][r]=0.f;

    loadT(0,0); CP_COMMIT();
    loadT(1,1); CP_COMMIT();

    for (int ch=0;ch<nk;ch++){
        CP_WAIT1();
        __syncthreads();
        if (ch+2<nk) loadT(ch+2,(ch+2)%3);
        CP_COMMIT();

        const uint32_t* au=(const uint32_t*)(As+(ch%3)*(128*20));
        const uint32_t* bu=(const uint32_t*)(Bs+(ch%3)*(16*136));
#pragma unroll
        for (int k8=0;k8<16;k8+=8){
            uint32_t a[4][4];
#pragma unroll
            for (int mi=0;mi<4;mi++){
                int r0=(warpM*64+mi*16+g)*20+k8+l4;
                a[mi][0]=au[r0];
                a[mi][1]=au[r0+8*20];
                a[mi][2]=au[r0+4];
                a[mi][3]=au[r0+8*20+4];
            }
            uint32_t bf[4][2];
#pragma unroll
            for (int ni=0;ni<4;ni++){
                int col=warpN*32+ni*8+g;
                bf[ni][0]=bu[(k8+l4)*136+col];
                bf[ni][1]=bu[(k8+4+l4)*136+col];
            }
#pragma unroll
            for (int mi=0;mi<4;mi++)
#pragma unroll
                for (int ni=0;ni<4;ni++)
                    MMA8(acc[mi][ni][0],acc[mi][ni][1],acc[mi][ni][2],acc[mi][ni][3],
                         a[mi][0],a[mi][1],a[mi][2],a[mi][3],bf[ni][0],bf[ni][1]);
        }
        __syncthreads();
    }

#pragma unroll
    for (int mi=0;mi<4;mi++){
        int row=by*128+warpM*64+mi*16+g;
#pragma unroll
        for (int ni=0;ni<4;ni++){
            int col=bx*128+warpN*32+ni*8+l4*2;
            float b0=bias[col], b1=bias[col+1];
            float2 r0,r1;
            r0.x=acc[mi][ni][0]+b0; r0.y=acc[mi][ni][1]+b1;
            r1.x=acc[mi][ni][2]+b0; r1.y=acc[mi][ni][3]+b1;
            if (ROUND){ r0.x=tf32r(r0.x); r0.y=tf32r(r0.y); r1.x=tf32r(r1.x); r1.y=tf32r(r1.y); }
            *(float2*)(C+(size_t)row*N+col)=r0;
            *(float2*)(C+(size_t)(row+8)*N+col)=r1;
        }
    }
}

// ---------- norm ----------
__global__ void norm_kernel(const float* __restrict__ pts, int P, float* __restrict__ nrm)
{
    __shared__ float sx[128], sy[128];
    int n=blockIdx.x, tid=threadIdx.x;
    const float* base=pts+(size_t)n*P*2;
    float ax=0.f, ay=0.f;
    for (int p=tid;p<P;p+=128){ ax+=base[2*p]; ay+=base[2*p+1]; }
    sx[tid]=ax; sy[tid]=ay;
    __syncthreads();
    for (int s=64;s>0;s>>=1){ if (tid<s){ sx[tid]+=sx[tid+s]; sy[tid]+=sy[tid+s]; } __syncthreads(); }
    float mx=sx[0]/(float)P, my=sy[0]/(float)P;
    __syncthreads();
    float am=0.f;
    for (int p=tid;p<P;p+=128)
        am=fmaxf(am,fmaxf(fabsf(base[2*p]-mx),fabsf(base[2*p+1]-my)));
    sx[tid]=am;
    __syncthreads();
    for (int s=64;s>0;s>>=1){ if (tid<s) sx[tid]=fmaxf(sx[tid],sx[tid+s]); __syncthreads(); }
    if (tid==0){ nrm[n*4]=mx; nrm[n*4+1]=my; nrm[n*4+2]=1.f/(sx[0]+1e-6f); }
}

// ---------- bilinear sample ----------
__global__ void sample_kernel(const float* __restrict__ feat, const float* __restrict__ pts,
                              const int* __restrict__ img_idx, const float* __restrict__ nrm,
                              float* __restrict__ xout, int P, int T)
{
    int warp=threadIdx.x>>5, lane=threadIdx.x&31;
    int t=blockIdx.x*8+warp;
    if (t>=T) return;
    int n=t/P;
    float px=pts[t*2], py=pts[t*2+1];
    int img=img_idx[n];
    float ix=px-0.5f, iy=py-0.5f;
    float x0f=floorf(ix), y0f=floorf(iy);
    float wx=ix-x0f, wy=iy-y0f;
    int x0=(int)x0f, y0=(int)y0f;
    float w00=(1.f-wx)*(1.f-wy), w10=wx*(1.f-wy), w01=(1.f-wx)*wy, w11=wx*wy;
    bool vx0=(x0>=0&&x0<WW), vx1=(x0+1>=0&&x0+1<WW);
    bool vy0=(y0>=0&&y0<HH), vy1=(y0+1>=0&&y0+1<HH);
    if (!(vx0&&vy0)) w00=0.f;
    if (!(vx1&&vy0)) w10=0.f;
    if (!(vx0&&vy1)) w01=0.f;
    if (!(vx1&&vy1)) w11=0.f;
    int xc0=min(max(x0,0),WW-1), xc1=min(max(x0+1,0),WW-1);
    int yc0=min(max(y0,0),HH-1), yc1=min(max(y0+1,0),HH-1);
    size_t b00=(((size_t)img*HH+yc0)*WW+xc0)*FEATPAD;
    size_t b10=(((size_t)img*HH+yc0)*WW+xc1)*FEATPAD;
    size_t b01=(((size_t)img*HH+yc1)*WW+xc0)*FEATPAD;
    size_t b11=(((size_t)img*HH+yc1)*WW+xc1)*FEATPAD;
    float* xr=xout+(size_t)t*DMODEL;
    for (int c=lane;c<FEATC;c+=32){
        xr[c]=tf32r(w00*feat[b00+c]+w10*feat[b10+c]+w01*feat[b01+c]+w11*feat[b11+c]);
    }
    if (lane==0){
        float mx=nrm[n*4], my=nrm[n*4+1], inv=nrm[n*4+2];
        xr[254]=tf32r((px-mx)*inv);
        xr[255]=tf32r((py-my)*inv);
    }
}

// ---------- attention via tf32 mma: block per (inst, head) ----------
__global__ __launch_bounds__(256)
void attn_tf32(const float* __restrict__ qkv, float* __restrict__ att, int P)
{
    extern __shared__ float sm[];
    float* Q=sm;               // [144][36]
    float* K=sm+144*36;        // [144][36]
    float* V=sm+2*144*36;      // [144][40]
    float* S=V+144*40;         // [144][140]

    int n=blockIdx.x, h=blockIdx.y;
    int tid=threadIdx.x, warp=tid>>5, lane=tid&31;
    int g=lane>>2, l4=lane&3;
    int mt=(P+15)>>4, nt=(P+7)>>3;

    for (int i=tid;i<144*8;i+=256){
        int p=i>>3, c=i&7;
        float4 vq=make_float4(0.f,0.f,0.f,0.f), vk=vq, vv=vq;
        if (p<P){
            const float* row=qkv+(size_t)(n*P+p)*768+h*32+c*4;
            vq=*(const float4*)(row);
            vk=*(const float4*)(row+256);
            vv=*(const float4*)(row+512);
        }
        *(float4*)(Q+p*36+c*4)=vq;
        *(float4*)(K+p*36+c*4)=vk;
        *(float4*)(V+p*40+c*4)=vv;
    }
    __syncthreads();

    const uint32_t* Qu=(const uint32_t*)Q;
    const uint32_t* Ku=(const uint32_t*)K;
    for (int t=warp;t<mt*nt;t+=8){
        int mi=t/nt, ni=t%nt;
        float c0=0.f,c1=0.f,c2=0.f,c3=0.f;
        int rq=mi*16+g, rk=ni*8+g;
#pragma unroll
        for (int k8=0;k8<32;k8+=8){
            uint32_t a0=Qu[rq*36+k8+l4];
            uint32_t a1=Qu[(rq+8)*36+k8+l4];
            uint32_t a2=Qu[rq*36+k8+4+l4];
            uint32_t a3=Qu[(rq+8)*36+k8+4+l4];
            uint32_t b0=Ku[rk*36+k8+l4];
            uint32_t b1=Ku[rk*36+k8+4+l4];
            MMA8(c0,c1,c2,c3,a0,a1,a2,a3,b0,b1);
        }
        int sr=mi*16+g, sc=ni*8+l4*2;
        *(float2*)(S+sr*140+sc)=make_float2(c0,c1);
        *(float2*)(S+(sr+8)*140+sc)=make_float2(c2,c3);
    }
    __syncthreads();

    const float QS=1.44269504088896340f*0.17677669529663689f;
    for (int p=warp;p<P;p+=8){
        float* row=S+p*140;
        float m=-1e30f;
        for (int j=lane;j<P;j+=32) m=fmaxf(m,row[j]);
#pragma unroll
        for (int off=16;off;off>>=1) m=fmaxf(m,__shfl_xor_sync(0xffffffffu,m,off));
        float l=0.f;
        for (int j=lane;j<P;j+=32){
            float e=exp2f((row[j]-m)*QS);
            row[j]=e; l+=e;
        }
#pragma unroll
        for (int off=16;off;off>>=1) l+=__shfl_xor_sync(0xffffffffu,l,off);
        float inv=1.f/l;
        for (int j=lane;j<nt*8;j+=32)
            row[j]=(j<P)?tf32r(row[j]*inv):0.f;
    }
    __syncthreads();

    const uint32_t* Su=(const uint32_t*)S;
    const uint32_t* Vu=(const uint32_t*)V;
    for (int t=warp;t<mt*4;t+=8){
        int mi=t>>2, ni=t&3;
        float c0=0.f,c1=0.f,c2=0.f,c3=0.f;
        int rs=mi*16+g;
        for (int kt=0;kt<nt;kt++){
            uint32_t a0=Su[rs*140+kt*8+l4];
            uint32_t a1=Su[(rs+8)*140+kt*8+l4];
            uint32_t a2=Su[rs*140+kt*8+4+l4];
            uint32_t a3=Su[(rs+8)*140+kt*8+4+l4];
            uint32_t b0=Vu[(kt*8+l4)*40+ni*8+g];
            uint32_t b1=Vu[(kt*8+4+l4)*40+ni*8+g];
            MMA8(c0,c1,c2,c3,a0,a1,a2,a3,b0,b1);
        }
        int row=mi*16+g, col=h*32+ni*8+l4*2;
        if (row<P)
            *(float2*)(att+(size_t)(n*P+row)*256+col)=make_float2(c0,c1);
        if (row+8<P)
            *(float2*)(att+(size_t)(n*P+row+8)*256+col)=make_float2(c2,c3);
    }
}

// ---------- fused head ----------
__global__ void head_kernel(const float* __restrict__ att, const float* __restrict__ wp,
                            const float* __restrict__ polyin, float* __restrict__ polyout,
                            float* __restrict__ outp, float strideF, int P, int stage1, int T)
{
    __shared__ float s_wp[514];
    for (int i=threadIdx.x;i<514;i+=128) s_wp[i]=wp[i];
    __syncthreads();
    int warp=threadIdx.x>>5, lane=threadIdx.x&31;
    int t=blockIdx.x*4+warp;
    if (t>=T) return;
    int n=t/P, p=t%P;
    const float* ar=att+(size_t)t*256;
    float a0=0.f, a1=0.f;
    for (int c=lane;c<256;c+=32){
        float av=ar[c];
        a0+=av*s_wp[2*c];
        a1+=av*s_wp[2*c+1];
    }
#pragma unroll
    for (int off=16;off;off>>=1){
        a0+=__shfl_down_sync(0xffffffffu,a0,off);
        a1+=__shfl_down_sync(0xffffffffu,a1,off);
    }
    if (lane==0){
        if (stage1&&p==0) return;
        int pidx=stage1?(n*NPOINT+p-1):(n*NPOINT+p);
        float ox=a0+s_wp[512], oy=a1+s_wp[513];
        float rx=ox*strideF+polyin[pidx*2];
        float ry=oy*strideF+polyin[pidx*2+1];
        if (polyout){ polyout[pidx*2]=rx; polyout[pidx*2+1]=ry; }
        outp[pidx*2]=rx*4.0f;
        outp[pidx*2+1]=ry*4.0f;
    }
}

// ---------- launch ----------
extern "C" void kernel_launch(void* const* d_in, const int* in_sizes, int n_in,
                              void* d_out, int out_size)
{
    const float* cnn=(const float*)d_in[0];
    const float* wh=(const float*)d_in[1];
    const int* ct_ind=(const int*)d_in[2];
    const int* ct_img=(const int*)d_in[3];
    const float* f1_w1=(const float*)d_in[4];
    const float* f1_b1=(const float*)d_in[5];
    const float* f1_w2=(const float*)d_in[6];
    const float* f1_b2=(const float*)d_in[7];
    const float* f2_w1=(const float*)d_in[8];
    const float* f2_b1=(const float*)d_in[9];
    const float* f2_w2=(const float*)d_in[10];
    const float* f2_b2=(const float*)d_in[11];
    const float* c1_wqkv=(const float*)d_in[12];
    const float* c1_bqkv=(const float*)d_in[13];
    const float* c1_wo=(const float*)d_in[14];
    const float* c1_bo=(const float*)d_in[15];
    const float* c1_wh=(const float*)d_in[16];
    const float* c1_bh=(const float*)d_in[17];
    const float* c2_wqkv=(const float*)d_in[18];
    const float* c2_bqkv=(const float*)d_in[19];
    const float* c2_wo=(const float*)d_in[20];
    const float* c2_bo=(const float*)d_in[21];
    const float* c2_wh=(const float*)d_in[22];
    const float* c2_bh=(const float*)d_in[23];
    float* out=(float*)d_out;

    void *p0,*p1,*p2,*p3,*p4,*p5,*p6,*p7,*p8,*p9,*pa,*pb,*pc,*pd,*pe,*pf;
    cudaGetSymbolAddress(&p0,g_int);    float* intt=(float*)p0;
    cudaGetSymbolAddress(&p1,g_tmp);    float* tmp=(float*)p1;
    cudaGetSymbolAddress(&p2,g_feat1);  float* feat1=(float*)p2;
    cudaGetSymbolAddress(&p3,g_feat2);  float* feat2=(float*)p3;
    cudaGetSymbolAddress(&p4,g_pts1);   float* pts1=(float*)p4;
    cudaGetSymbolAddress(&p5,g_init);   float* initp=(float*)p5;
    cudaGetSymbolAddress(&p6,g_coarse); float* coarse=(float*)p6;
    cudaGetSymbolAddress(&p7,g_nrm);    float* nrm=(float*)p7;
    cudaGetSymbolAddress(&p8,g_x);      float* xbuf=(float*)p8;
    cudaGetSymbolAddress(&p9,g_qkv);    float* qkv=(float*)p9;
    cudaGetSymbolAddress(&pa,g_att);    float* att=(float*)pa;
    cudaGetSymbolAddress(&pb,g_wt);     float* wt=(float*)pb;
    cudaGetSymbolAddress(&pc,g_w2t);    float* w2t=(float*)pc;
    cudaGetSymbolAddress(&pd,g_b2p);    float* b2p=(float*)pd;
    cudaGetSymbolAddress(&pe,g_wq);     float* wq=(float*)pe;
    cudaGetSymbolAddress(&pf,g_wp1);    float* wp1=(float*)pf;
    void* pg; cudaGetSymbolAddress(&pg,g_wp2); float* wp2=(float*)pg;

    const int CONV_SMEM=(180*68+3*16*136)*4;
    const int GEMM_SMEM=(3*128*20+3*16*136)*4;
    const int ATTN_SMEM=(2*144*36+144*40+144*140)*4;
    cudaFuncSetAttribute(conv3_tf32, cudaFuncAttributeMaxDynamicSharedMemorySize, CONV_SMEM);
    cudaFuncSetAttribute(gemm_tf32<false>, cudaFuncAttributeMaxDynamicSharedMemorySize, GEMM_SMEM);
    cudaFuncSetAttribute(gemm_tf32<true>,  cudaFuncAttributeMaxDynamicSharedMemorySize, GEMM_SMEM);
    cudaFuncSetAttribute(attn_tf32, cudaFuncAttributeMaxDynamicSharedMemorySize, ATTN_SMEM);

    fuse_head_kernel<<<1,256>>>(c1_wo,c1_bo,c1_wh,c1_bh,wp1);
    fuse_head_kernel<<<1,256>>>(c2_wo,c2_bo,c2_wh,c2_bh,wp2);
    init_kernel<<<NINST,128>>>(wh,ct_ind,ct_img,pts1,initp,out);
    transpose_kernel<<<1024,256>>>(cnn,intt);

    // feature pyramid 1
    prep_wt_kernel<<<576,256>>>(f1_w1,wt);
    prep_w2_kernel<<<256,256>>>(f1_w2,f1_b2,w2t,b2p);
    conv3_tf32<<<dim3(1024,2),256,CONV_SMEM>>>(intt,wt,f1_b1,tmp);
    gemm_tf32<false><<<dim3(2,PIX/128),256,GEMM_SMEM>>>(tmp,w2t,b2p,feat1,PIX,256,256);
    // feature pyramid 2
    prep_wt_kernel<<<576,256>>>(f2_w1,wt);
    conv3_tf32<<<dim3(1024,2),256,CONV_SMEM>>>(intt,wt,f2_b1,tmp);
    prep_w2_kernel<<<256,256>>>(f2_w2,f2_b2,w2t,b2p);
    gemm_tf32<false><<<dim3(2,PIX/128),256,GEMM_SMEM>>>(tmp,w2t,b2p,feat2,PIX,256,256);

    // ---- stage 1 ----
    norm_kernel<<<NINST,128>>>(pts1,P1,nrm);
    sample_kernel<<<(T1+7)/8,256>>>(feat1,pts1,ct_img,nrm,xbuf,P1,T1);
    prep_wq_kernel<<<192,256>>>(c1_wqkv,wq);
    gemm_tf32<true><<<dim3(6,T1/128),256,GEMM_SMEM>>>(xbuf,wq,c1_bqkv,qkv,T1,768,256);
    attn_tf32<<<dim3(NINST,8),256,ATTN_SMEM>>>(qkv,att,P1);
    head_kernel<<<(T1+3)/4,128>>>(att,wp1,initp,coarse,out+NINST*NPOINT*2,4.0f,P1,1,T1);

    // ---- stage 2 ----
    norm_kernel<<<NINST,128>>>(coarse,P2,nrm);
    sample_kernel<<<(T2+7)/8,256>>>(feat2,coarse,ct_img,nrm,xbuf,P2,T2);
    prep_wq_kernel<<<192,256>>>(c2_wqkv,wq);
    gemm_tf32<true><<<dim3(6,T2/128),256,GEMM_SMEM>>>(xbuf,wq,c2_bqkv,qkv,T2,768,256);
    attn_tf32<<<dim3(NINST,8),256,ATTN_SMEM>>>(qkv,att,P2);
    head_kernel<<<(T2+3)/4,128>>>(att,wp2,coarse,nullptr,out+2*NINST*NPOINT*2,1.0f,P2,0,T2);
}